// round 1
// baseline (speedup 1.0000x reference)
#include <cuda_runtime.h>
#include <math.h>
#include <stdint.h>

// Problem dims
#define BSZ  256
#define TLEN 256
#define NINV 128
#define HV   256
#define GV   768   // 3H
#define H2V  512   // 2H

// ---------------- device scratch (no allocations allowed) ----------------
__device__ float g_wihT1f[NINV * GV];
__device__ float g_wihT1r[NINV * GV];
__device__ float g_wihT2f[H2V * GV];
__device__ float g_wihT2r[H2V * GV];
__device__ float g_whhT1f[HV * GV];
__device__ float g_whhT1r[HV * GV];
__device__ float g_whhT2f[HV * GV];
__device__ float g_whhT2r[HV * GV];
__device__ float g_bihP[4][GV];   // 0=1f 1=1r 2=2f 3=2r
__device__ float g_bhhP[4][GV];
__device__ float g_xgf[TLEN * BSZ * GV];   // packed input gates, fwd dir (reused per layer)
__device__ float g_xgr[TLEN * BSZ * GV];   // reverse dir
__device__ float g_rec1[BSZ * TLEN * H2V];
__device__ float g_rec2[BSZ * TLEN * H2V];
__device__ float g_h[2][2][BSZ * HV];      // [buf][dir][b*H+k]
__device__ unsigned g_cnt;
__device__ volatile unsigned g_gen;

// Packed column mapping: c = jt*96 + gate*32 + jl  <->  orig row = gate*256 + jt*32 + jl
__device__ __forceinline__ int orig_row(int c) {
    int g  = (c % 96) >> 5;
    int jt = c / 96;
    int jl = c & 31;
    return g * HV + jt * 32 + jl;
}

// ---------------- weight / bias packing ----------------
__global__ void pack_w(float* __restrict__ dst, const float* __restrict__ src, int Din) {
    int tot = Din * GV;
    for (int idx = blockIdx.x * blockDim.x + threadIdx.x; idx < tot;
         idx += gridDim.x * blockDim.x) {
        int d = idx / GV;
        int c = idx - d * GV;
        dst[idx] = src[orig_row(c) * Din + d];   // dst[d][c] = src[orig(c)][d]
    }
}

__global__ void pack_b(float* __restrict__ dst, const float* __restrict__ src) {
    int c = threadIdx.x;
    if (c < GV) dst[c] = src[orig_row(c)];
}

__global__ void zero_h() {
    int idx = blockIdx.x * blockDim.x + threadIdx.x;
    if (idx < 2 * BSZ * HV) ((float*)g_h)[idx] = 0.0f;   // zeroes buf0, both dirs
}

// ---------------- input-gate GEMM ----------------
// out[t*BSZ*GV + b*GV + n] = sum_k A[(b*TLEN+t)*K + k] * Wt[k*GV+n] + bias[n]
template <int K>
__global__ void __launch_bounds__(256) xg_gemm(const float* __restrict__ A,
                                               const float* __restrict__ Wt,
                                               const float* __restrict__ bias,
                                               float* __restrict__ out) {
    __shared__ float sA[16][68];   // [k][m], padded for alignment
    __shared__ float sB[16][64];   // [k][n]
    int tid = threadIdx.x;
    int m0 = blockIdx.x * 64;
    int n0 = blockIdx.y * 64;
    int tx = tid & 15, ty = tid >> 4;

    int ar = tid >> 2;            // 0..63 row of A tile
    int ak = (tid & 3) * 4;       // k offset
    int bk = tid >> 4;            // 0..15 k row of B tile
    int bc = (tid & 15) * 4;      // 0..60 col

    const float* Aptr = A + (size_t)(m0 + ar) * K + ak;
    const float* Bptr = Wt + (size_t)bk * GV + n0 + bc;

    float acc[4][4] = {};
    for (int k0 = 0; k0 < K; k0 += 16) {
        float4 av = *(const float4*)(Aptr + k0);
        float4 bv = *(const float4*)(Bptr + (size_t)k0 * GV);
        __syncthreads();
        sA[ak + 0][ar] = av.x;
        sA[ak + 1][ar] = av.y;
        sA[ak + 2][ar] = av.z;
        sA[ak + 3][ar] = av.w;
        *(float4*)&sB[bk][bc] = bv;
        __syncthreads();
#pragma unroll
        for (int kk = 0; kk < 16; kk++) {
            float4 a = *(const float4*)&sA[kk][ty * 4];
            float4 b = *(const float4*)&sB[kk][tx * 4];
            acc[0][0] += a.x * b.x; acc[0][1] += a.x * b.y; acc[0][2] += a.x * b.z; acc[0][3] += a.x * b.w;
            acc[1][0] += a.y * b.x; acc[1][1] += a.y * b.y; acc[1][2] += a.y * b.z; acc[1][3] += a.y * b.w;
            acc[2][0] += a.z * b.x; acc[2][1] += a.z * b.y; acc[2][2] += a.z * b.z; acc[2][3] += a.z * b.w;
            acc[3][0] += a.w * b.x; acc[3][1] += a.w * b.y; acc[3][2] += a.w * b.z; acc[3][3] += a.w * b.w;
        }
    }
    float4 b4 = *(const float4*)&bias[n0 + tx * 4];
#pragma unroll
    for (int i = 0; i < 4; i++) {
        int mm = m0 + ty * 4 + i;
        int b = mm >> 8;          // TLEN = 256
        int t = mm & 255;
        float4 o;
        o.x = acc[i][0] + b4.x; o.y = acc[i][1] + b4.y;
        o.z = acc[i][2] + b4.z; o.w = acc[i][3] + b4.w;
        *(float4*)&out[((size_t)t * BSZ + b) * GV + n0 + tx * 4] = o;
    }
}

// ---------------- grid barrier (all CTAs resident: grid = 128 <= 148) ----------------
__device__ __forceinline__ void grid_barrier() {
    __syncthreads();
    if (threadIdx.x == 0) {
        __threadfence();
        unsigned my = g_gen;
        unsigned t = atomicAdd(&g_cnt, 1u);
        if (t == gridDim.x - 1) {
            g_cnt = 0u;
            __threadfence();
            g_gen = my + 1u;
        } else {
            while (g_gen == my) { }
        }
        __threadfence();
    }
    __syncthreads();
}

// ---------------- recurrent scan: both directions of one layer ----------------
// Grid = 128 CTAs: dir = blockIdx.x>>6; tile = blockIdx.x&63 -> (batch-tile 32) x (j-tile 32, 3 gates = 96 cols)
// Whh tile (96KB) persistent in SMEM. One grid barrier per timestep.
#define SCAN_SMEM_FLOATS (256 * 96 + 256 * 36 + 32 * 96)
__global__ void __launch_bounds__(192, 1) scan_kernel(const float* __restrict__ WhTf,
                                                      const float* __restrict__ WhTr,
                                                      const float* __restrict__ bhf,
                                                      const float* __restrict__ bhr,
                                                      const float* __restrict__ xgF,
                                                      const float* __restrict__ xgR,
                                                      float* __restrict__ recOut) {
    extern __shared__ float sm[];
    float* sW = sm;                 // [256][96]
    float* sH = sm + 256 * 96;      // [256][36] (padded), h transposed [k][b]
    float* sG = sH + 256 * 36;      // [32][96] hg + bhh

    int tid = threadIdx.x;
    int dir = blockIdx.x >> 6;
    int tile = blockIdx.x & 63;
    int bt = tile >> 3, jt = tile & 7;
    int b0 = bt * 32, j0 = jt * 32, C0 = jt * 96;

    const float* W  = dir ? WhTr : WhTf;
    const float* bh = dir ? bhr : bhf;
    const float* xg = dir ? xgR : xgF;

    // load persistent Whh slice [k=0..255][C0..C0+95]
    for (int idx = tid; idx < 256 * 96; idx += 192) {
        int k = idx / 96, c = idx - k * 96;
        sW[idx] = W[(size_t)k * GV + C0 + c];
    }

    int txg = tid % 24, tyg = tid / 24;   // 24 x 8 thread grid, 4x4 micro-tile
    float bj[4];
#pragma unroll
    for (int j = 0; j < 4; j++) bj[j] = bh[C0 + txg * 4 + j];

    int cur = 0;
    for (int step = 0; step < TLEN; step++) {
        int t = dir ? (TLEN - 1 - step) : step;
        const float* hc = g_h[cur][dir];
        float* hnx = g_h[cur ^ 1][dir];

        // load h tile transposed: sH[k][b] = h[b0+b][k]
        for (int idx = tid; idx < 32 * 256; idx += 192) {
            int b = idx >> 8, k = idx & 255;
            sH[k * 36 + b] = hc[(b0 + b) * HV + k];
        }
        __syncthreads();

        float acc[4][4] = {};
#pragma unroll 4
        for (int k = 0; k < 256; k++) {
            float4 a = *(const float4*)&sH[k * 36 + tyg * 4];
            float4 w = *(const float4*)&sW[k * 96 + txg * 4];
            acc[0][0] += a.x * w.x; acc[0][1] += a.x * w.y; acc[0][2] += a.x * w.z; acc[0][3] += a.x * w.w;
            acc[1][0] += a.y * w.x; acc[1][1] += a.y * w.y; acc[1][2] += a.y * w.z; acc[1][3] += a.y * w.w;
            acc[2][0] += a.z * w.x; acc[2][1] += a.z * w.y; acc[2][2] += a.z * w.z; acc[2][3] += a.z * w.w;
            acc[3][0] += a.w * w.x; acc[3][1] += a.w * w.y; acc[3][2] += a.w * w.z; acc[3][3] += a.w * w.w;
        }
#pragma unroll
        for (int i = 0; i < 4; i++)
#pragma unroll
            for (int j = 0; j < 4; j++)
                sG[(tyg * 4 + i) * 96 + txg * 4 + j] = acc[i][j] + bj[j];
        __syncthreads();

        // fused GRU nonlinearity for this (batch, j) tile
        const float* xgrow = xg + ((size_t)t * BSZ + b0) * GV + C0;
        for (int idx = tid; idx < 1024; idx += 192) {
            int b = idx >> 5, j = idx & 31;
            const float* xp = xgrow + (size_t)b * GV;
            float xr = xp[j], xz = xp[32 + j], xn = xp[64 + j];
            float hr = sG[b * 96 + j];
            float hz = sG[b * 96 + 32 + j];
            float hn = sG[b * 96 + 64 + j];
            float r = 1.0f / (1.0f + expf(-(xr + hr)));
            float z = 1.0f / (1.0f + expf(-(xz + hz)));
            float n = tanhf(xn + r * hn);
            float hold = sH[(j0 + j) * 36 + b];
            float hv = (1.0f - z) * n + z * hold;
            hnx[(b0 + b) * HV + j0 + j] = hv;
            recOut[((size_t)(b0 + b) * TLEN + t) * H2V + dir * HV + j0 + j] = hv;
        }
        grid_barrier();
        cur ^= 1;
    }
}

// ---------------- attention + output ----------------
__global__ void __launch_bounds__(256) attention_kernel(const float* __restrict__ rec2,
                                                        float* __restrict__ out) {
    __shared__ float smerged[512];
    __shared__ float sc[256];
    __shared__ float red[8];
    __shared__ float bcast;
    int b = blockIdx.x, tid = threadIdx.x;
    const float* base = rec2 + (size_t)b * (TLEN * H2V);

    smerged[tid]       = base[255 * H2V + tid];        // h2f final
    smerged[256 + tid] = base[256 + tid];              // h2r final (t=0 row, cols 256..511)
    __syncthreads();

    int lane = tid & 31, wid = tid >> 5;
    for (int t = wid; t < TLEN; t += 8) {
        const float* row = base + (size_t)t * H2V;
        float s = 0.0f;
        for (int h = lane; h < H2V; h += 32) s += row[h] * smerged[h];
#pragma unroll
        for (int o = 16; o; o >>= 1) s += __shfl_xor_sync(0xffffffffu, s, o);
        if (lane == 0) sc[t] = s;
    }
    __syncthreads();

    float v = sc[tid];
    float m = v;
#pragma unroll
    for (int o = 16; o; o >>= 1) m = fmaxf(m, __shfl_xor_sync(0xffffffffu, m, o));
    if (lane == 0) red[wid] = m;
    __syncthreads();
    if (tid == 0) {
        float mm = red[0];
        for (int i = 1; i < 8; i++) mm = fmaxf(mm, red[i]);
        bcast = mm;
    }
    __syncthreads();
    m = bcast;
    float e = expf(v - m);
    float s = e;
#pragma unroll
    for (int o = 16; o; o >>= 1) s += __shfl_xor_sync(0xffffffffu, s, o);
    if (lane == 0) red[wid] = s;
    __syncthreads();
    if (tid == 0) {
        float ss = 0.0f;
        for (int i = 0; i < 8; i++) ss += red[i];
        bcast = ss;
    }
    __syncthreads();
    float w = e / bcast;
    sc[tid] = w;
    __syncthreads();

    float a0 = 0.0f, a1 = 0.0f;
    for (int t = 0; t < TLEN; t++) {
        float wt = sc[t];
        a0 += wt * base[(size_t)t * H2V + tid];
        a1 += wt * base[(size_t)t * H2V + 256 + tid];
    }
    float* ob = out + (size_t)b * 1024;
    ob[tid]       = a0;
    ob[256 + tid] = a1;
    ob[512 + tid] = base[255 * H2V + tid];
    ob[768 + tid] = base[255 * H2V + 256 + tid];
}

// ---------------- host launcher ----------------
extern "C" void kernel_launch(void* const* d_in, const int* in_sizes, int n_in,
                              void* d_out, int out_size) {
    (void)in_sizes; (void)n_in; (void)out_size;
    const float* input = (const float*)d_in[0];
    const float* wih1f = (const float*)d_in[1];
    const float* whh1f = (const float*)d_in[2];
    const float* bih1f = (const float*)d_in[3];
    const float* bhh1f = (const float*)d_in[4];
    const float* wih1r = (const float*)d_in[5];
    const float* whh1r = (const float*)d_in[6];
    const float* bih1r = (const float*)d_in[7];
    const float* bhh1r = (const float*)d_in[8];
    const float* wih2f = (const float*)d_in[9];
    const float* whh2f = (const float*)d_in[10];
    const float* bih2f = (const float*)d_in[11];
    const float* bhh2f = (const float*)d_in[12];
    const float* wih2r = (const float*)d_in[13];
    const float* whh2r = (const float*)d_in[14];
    const float* bih2r = (const float*)d_in[15];
    const float* bhh2r = (const float*)d_in[16];

    float *wT1f, *wT1r, *wT2f, *wT2r, *hT1f, *hT1r, *hT2f, *hT2r;
    float *bihP, *bhhP, *xgf, *xgr, *rec1, *rec2;
    cudaGetSymbolAddress((void**)&wT1f, g_wihT1f);
    cudaGetSymbolAddress((void**)&wT1r, g_wihT1r);
    cudaGetSymbolAddress((void**)&wT2f, g_wihT2f);
    cudaGetSymbolAddress((void**)&wT2r, g_wihT2r);
    cudaGetSymbolAddress((void**)&hT1f, g_whhT1f);
    cudaGetSymbolAddress((void**)&hT1r, g_whhT1r);
    cudaGetSymbolAddress((void**)&hT2f, g_whhT2f);
    cudaGetSymbolAddress((void**)&hT2r, g_whhT2r);
    cudaGetSymbolAddress((void**)&bihP, g_bihP);
    cudaGetSymbolAddress((void**)&bhhP, g_bhhP);
    cudaGetSymbolAddress((void**)&xgf, g_xgf);
    cudaGetSymbolAddress((void**)&xgr, g_xgr);
    cudaGetSymbolAddress((void**)&rec1, g_rec1);
    cudaGetSymbolAddress((void**)&rec2, g_rec2);

    // pack weights/biases
    pack_w<<<128, 256>>>(wT1f, wih1f, NINV);
    pack_w<<<128, 256>>>(wT1r, wih1r, NINV);
    pack_w<<<256, 256>>>(wT2f, wih2f, H2V);
    pack_w<<<256, 256>>>(wT2r, wih2r, H2V);
    pack_w<<<128, 256>>>(hT1f, whh1f, HV);
    pack_w<<<128, 256>>>(hT1r, whh1r, HV);
    pack_w<<<128, 256>>>(hT2f, whh2f, HV);
    pack_w<<<128, 256>>>(hT2r, whh2r, HV);
    pack_b<<<1, 768>>>(bihP + 0 * GV, bih1f);
    pack_b<<<1, 768>>>(bihP + 1 * GV, bih1r);
    pack_b<<<1, 768>>>(bihP + 2 * GV, bih2f);
    pack_b<<<1, 768>>>(bihP + 3 * GV, bih2r);
    pack_b<<<1, 768>>>(bhhP + 0 * GV, bhh1f);
    pack_b<<<1, 768>>>(bhhP + 1 * GV, bhh1r);
    pack_b<<<1, 768>>>(bhhP + 2 * GV, bhh2f);
    pack_b<<<1, 768>>>(bhhP + 3 * GV, bhh2r);

    size_t scan_smem = SCAN_SMEM_FLOATS * sizeof(float);
    cudaFuncSetAttribute(scan_kernel, cudaFuncAttributeMaxDynamicSharedMemorySize,
                         (int)scan_smem);

    // Layer 1
    xg_gemm<NINV><<<dim3(1024, 12), 256>>>(input, wT1f, bihP + 0 * GV, xgf);
    xg_gemm<NINV><<<dim3(1024, 12), 256>>>(input, wT1r, bihP + 1 * GV, xgr);
    zero_h<<<512, 256>>>();
    scan_kernel<<<128, 192, scan_smem>>>(hT1f, hT1r, bhhP + 0 * GV, bhhP + 1 * GV,
                                         xgf, xgr, rec1);
    // Layer 2
    xg_gemm<H2V><<<dim3(1024, 12), 256>>>(rec1, wT2f, bihP + 2 * GV, xgf);
    xg_gemm<H2V><<<dim3(1024, 12), 256>>>(rec1, wT2r, bihP + 3 * GV, xgr);
    zero_h<<<512, 256>>>();
    scan_kernel<<<128, 192, scan_smem>>>(hT2f, hT2r, bhhP + 2 * GV, bhhP + 3 * GV,
                                         xgf, xgr, rec2);
    // Attention + output
    attention_kernel<<<256, 256>>>(rec2, (float*)d_out);
}

// round 3
// speedup vs baseline: 1.2150x; 1.2150x over previous
#include <cuda_runtime.h>
#include <math.h>
#include <stdint.h>

// Problem dims
#define BSZ  256
#define TLEN 256
#define NINV 128
#define HV   256
#define GV   768   // 3H
#define H2V  512   // 2H

// ---------------- device scratch (no allocations allowed) ----------------
// Weight fragments, layout [96 ntiles][K/8 ksteps][32 lanes] float4 {b0h,b1h,b0l,b1l}
__device__ float4 g_fW1f[96 * 16 * 32];   // wih layer1 Din=128
__device__ float4 g_fW1r[96 * 16 * 32];
__device__ float4 g_fW2f[96 * 64 * 32];   // wih layer2 Din=512
__device__ float4 g_fW2r[96 * 64 * 32];
__device__ float4 g_fH1f[96 * 32 * 32];   // whh Din=256
__device__ float4 g_fH1r[96 * 32 * 32];
__device__ float4 g_fH2f[96 * 32 * 32];
__device__ float4 g_fH2r[96 * 32 * 32];
__device__ float g_bihP[4][GV];   // 0=1f 1=1r 2=2f 3=2r (packed col order)
__device__ float g_bhhP[4][GV];
__device__ float g_xgf[TLEN * BSZ * GV];
__device__ float g_xgr[TLEN * BSZ * GV];
__device__ float g_rec1[BSZ * TLEN * H2V];
__device__ float g_rec2[BSZ * TLEN * H2V];
__device__ float g_h[2][2][BSZ * HV];
__device__ unsigned g_cnt;
__device__ volatile unsigned g_gen;

// Packed column mapping: c = jt*96 + gate*32 + jl  <->  orig row = gate*256 + jt*32 + jl
__device__ __forceinline__ int orig_row(int c) {
    int g  = (c % 96) >> 5;
    int jt = c / 96;
    int jl = c & 31;
    return g * HV + jt * 32 + jl;
}

// ---------------- tf32 helpers ----------------
__device__ __forceinline__ float tf32_rnd(float x) {
    uint32_t u;
    asm("cvt.rna.tf32.f32 %0, %1;" : "=r"(u) : "f"(x));
    return __uint_as_float(u);
}
__device__ __forceinline__ void split1(float x, uint32_t& h, uint32_t& l) {
    uint32_t hb;
    asm("cvt.rna.tf32.f32 %0, %1;" : "=r"(hb) : "f"(x));
    float lf = x - __uint_as_float(hb);
    uint32_t lb;
    asm("cvt.rna.tf32.f32 %0, %1;" : "=r"(lb) : "f"(lf));
    h = hb; l = lb;
}
__device__ __forceinline__ void mma8(float* c, const uint32_t* a, uint32_t b0, uint32_t b1) {
    asm("mma.sync.aligned.m16n8k8.row.col.f32.tf32.tf32.f32 "
        "{%0,%1,%2,%3},{%4,%5,%6,%7},{%8,%9},{%0,%1,%2,%3};"
        : "+f"(c[0]), "+f"(c[1]), "+f"(c[2]), "+f"(c[3])
        : "r"(a[0]), "r"(a[1]), "r"(a[2]), "r"(a[3]), "r"(b0), "r"(b1));
}

// ---------------- packing ----------------
// B fragments: value(k, n): b0 at (k = ks*8 + lane%4, n = nt*8 + lane/4), b1 at k+4.
// B[k][c] = W[orig_row(c)][k].
__global__ void pack_frag(float4* __restrict__ dst, const float* __restrict__ src, int Din) {
    int KS = Din >> 3;
    int tot = 96 * KS * 32;
    for (int idx = blockIdx.x * blockDim.x + threadIdx.x; idx < tot;
         idx += gridDim.x * blockDim.x) {
        int lane = idx & 31;
        int ks = (idx >> 5) % KS;
        int nt = idx / (32 * KS);
        int cg = nt * 8 + (lane >> 2);
        int r = orig_row(cg);
        int k0 = ks * 8 + (lane & 3);
        float v0 = src[(size_t)r * Din + k0];
        float v1 = src[(size_t)r * Din + k0 + 4];
        float h0 = tf32_rnd(v0), l0 = tf32_rnd(v0 - h0);
        float h1 = tf32_rnd(v1), l1 = tf32_rnd(v1 - h1);
        dst[idx] = make_float4(h0, h1, l0, l1);
    }
}

__global__ void pack_b(float* __restrict__ dst, const float* __restrict__ src) {
    int c = threadIdx.x;
    if (c < GV) dst[c] = src[orig_row(c)];
}

__global__ void zero_h() {
    int idx = blockIdx.x * blockDim.x + threadIdx.x;
    if (idx < 2 * BSZ * HV) ((float*)g_h)[idx] = 0.0f;
}

// ---------------- input-gate GEMM (tensor cores, split tf32) ----------------
// out[(t*BSZ+b)*GV + n] = sum_k A[(b*T+t)*K + k] * W[k][n] + bias[n]
// grid: (12 nblk, 1024 mblk); block 128 (4 warps); CTA tile 64x64, k-chunk 64.
#define XG_SMEM (64 * 68 * 4 + 8 * 8 * 32 * 16)   // sA 17408 + sB 32768 = 50176
extern __shared__ char smem_raw[];

template <int K>
__global__ void __launch_bounds__(128) xg_mma(const float* __restrict__ A,
                                              const float4* __restrict__ fB,
                                              const float* __restrict__ bias,
                                              float* __restrict__ out) {
    float* sA = (float*)smem_raw;                       // [64][68]
    float4* sB = (float4*)(smem_raw + 64 * 68 * 4);     // [8 nt][8 ks][32]
    const int KSTEPS = K >> 3;

    int tid = threadIdx.x;
    int w = tid >> 5, lane = tid & 31;
    int m0 = blockIdx.y * 64;
    int n0blk = blockIdx.x * 8;          // global ntile base
    int wm = (w & 1) * 32;               // warp row base
    int wn = (w >> 1) * 4;               // warp local ntile base (4 ntiles)
    int r = lane >> 2, cc = lane & 3;

    float acc[2][4][4] = {};

    for (int kc = 0; kc < K; kc += 64) {
        __syncthreads();
        for (int idx = tid; idx < 64 * 16; idx += 128) {
            int rr = idx >> 4, c4 = (idx & 15) * 4;
            float4 v = *(const float4*)&A[(size_t)(m0 + rr) * K + kc + c4];
            *(float4*)&sA[rr * 68 + c4] = v;
        }
        for (int idx = tid; idx < 8 * 8 * 32; idx += 128) {
            int nt = idx >> 8;
            int ks = (idx >> 5) & 7;
            int ln = idx & 31;
            sB[idx] = fB[((size_t)(n0blk + nt) * KSTEPS + (kc >> 3) + ks) * 32 + ln];
        }
        __syncthreads();
#pragma unroll
        for (int ks = 0; ks < 8; ks++) {
            int k0 = ks * 8;
            uint32_t ah[2][4], al[2][4];
#pragma unroll
            for (int mi = 0; mi < 2; mi++) {
                float e0 = sA[(wm + mi * 16 + r) * 68 + k0 + cc];
                float e1 = sA[(wm + mi * 16 + r + 8) * 68 + k0 + cc];
                float e2 = sA[(wm + mi * 16 + r) * 68 + k0 + cc + 4];
                float e3 = sA[(wm + mi * 16 + r + 8) * 68 + k0 + cc + 4];
                split1(e0, ah[mi][0], al[mi][0]);
                split1(e1, ah[mi][1], al[mi][1]);
                split1(e2, ah[mi][2], al[mi][2]);
                split1(e3, ah[mi][3], al[mi][3]);
            }
#pragma unroll
            for (int ni = 0; ni < 4; ni++) {
                float4 bb = sB[((wn + ni) * 8 + ks) * 32 + lane];
                uint32_t bh0 = __float_as_uint(bb.x), bh1 = __float_as_uint(bb.y);
                uint32_t bl0 = __float_as_uint(bb.z), bl1 = __float_as_uint(bb.w);
#pragma unroll
                for (int mi = 0; mi < 2; mi++) {
                    mma8(acc[mi][ni], ah[mi], bh0, bh1);
                    mma8(acc[mi][ni], al[mi], bh0, bh1);
                    mma8(acc[mi][ni], ah[mi], bl0, bl1);
                }
            }
        }
    }
    // epilogue: D[row][col], row m = b*256+t, output layout [t][b][GV]
#pragma unroll
    for (int mi = 0; mi < 2; mi++) {
#pragma unroll
        for (int half = 0; half < 2; half++) {
            int row = m0 + wm + mi * 16 + r + half * 8;
            int b = row >> 8, t = row & 255;
            float* orow = out + ((size_t)t * BSZ + b) * GV;
#pragma unroll
            for (int ni = 0; ni < 4; ni++) {
                int col = (n0blk + wn + ni) * 8 + 2 * cc;
                float2 bs = *(const float2*)&bias[col];
                float2 o;
                o.x = acc[mi][ni][half * 2 + 0] + bs.x;
                o.y = acc[mi][ni][half * 2 + 1] + bs.y;
                *(float2*)&orow[col] = o;
            }
        }
    }
}

// ---------------- grid barrier ----------------
__device__ __forceinline__ void grid_barrier() {
    __syncthreads();
    if (threadIdx.x == 0) {
        __threadfence();
        unsigned my = g_gen;
        unsigned t = atomicAdd(&g_cnt, 1u);
        if (t == gridDim.x - 1) {
            g_cnt = 0u;
            __threadfence();
            g_gen = my + 1u;
        } else {
            while (g_gen == my) { }
        }
        __threadfence();
    }
    __syncthreads();
}

// ---------------- recurrent scan (tensor cores) ----------------
// 128 CTAs: dir = bid>>6; bt = (bid&63)>>3 (batch tile 32), jt = bid&7 (96 packed cols).
// Whh fragments (hi+lo) pinned in SMEM; one grid barrier per timestep.
#define SCAN_SMEM (12 * 32 * 32 * 16 + 32 * 260 * 4)   // 196608 + 33280 = 229888
__global__ void __launch_bounds__(192, 1) scan_kernel(const float4* __restrict__ fWf,
                                                      const float4* __restrict__ fWr,
                                                      const float* __restrict__ bhf,
                                                      const float* __restrict__ bhr,
                                                      const float* __restrict__ xgF,
                                                      const float* __restrict__ xgR,
                                                      float* __restrict__ recOut) {
    float4* sB4 = (float4*)smem_raw;                      // [12 nt][32 ks][32] f4
    float* sH = (float*)(smem_raw + 12 * 32 * 32 * 16);   // [32][260] fp32 (A tile)
    float* sG = sH;                                       // aliased after MMA
    __shared__ float sbh[96];

    int tid = threadIdx.x;
    int w = tid >> 5, lane = tid & 31;
    int dir = blockIdx.x >> 6;
    int tile = blockIdx.x & 63;
    int bt = tile >> 3, jt = tile & 7;
    int b0 = bt * 32, j0 = jt * 32, C0 = jt * 96;

    const float4* fW = dir ? fWr : fWf;
    const float* bh = dir ? bhr : bhf;
    const float* xg = dir ? xgR : xgF;

    // load persistent Whh fragment slice (ntiles jt*12 .. jt*12+11)
    for (int idx = tid; idx < 12 * 32 * 32; idx += 192)
        sB4[idx] = fW[(size_t)jt * 12 * 32 * 32 + idx];
    if (tid < 96) sbh[tid] = bh[C0 + tid];

    int r = lane >> 2, cc = lane & 3;
    int cur = 0;
    for (int step = 0; step < TLEN; step++) {
        int t = dir ? (TLEN - 1 - step) : step;
        const float* hc = g_h[cur][dir];
        float* hnx = g_h[cur ^ 1][dir];

        // load h tile [32][256] row-major (stride 260)
        for (int idx = tid; idx < 2048; idx += 192) {
            int b = idx >> 6, kq = (idx & 63) * 4;
            float4 v = *(const float4*)&hc[(size_t)(b0 + b) * HV + kq];
            *(float4*)&sH[b * 260 + kq] = v;
        }
        __syncthreads();

        float acc[2][2][4] = {};
#pragma unroll 4
        for (int ks = 0; ks < 32; ks++) {
            int k0 = ks * 8;
            uint32_t ah[2][4], al[2][4];
#pragma unroll
            for (int mi = 0; mi < 2; mi++) {
                float e0 = sH[(mi * 16 + r) * 260 + k0 + cc];
                float e1 = sH[(mi * 16 + r + 8) * 260 + k0 + cc];
                float e2 = sH[(mi * 16 + r) * 260 + k0 + cc + 4];
                float e3 = sH[(mi * 16 + r + 8) * 260 + k0 + cc + 4];
                split1(e0, ah[mi][0], al[mi][0]);
                split1(e1, ah[mi][1], al[mi][1]);
                split1(e2, ah[mi][2], al[mi][2]);
                split1(e3, ah[mi][3], al[mi][3]);
            }
#pragma unroll
            for (int ni = 0; ni < 2; ni++) {
                float4 bb = sB4[((2 * w + ni) * 32 + ks) * 32 + lane];
                uint32_t bh0 = __float_as_uint(bb.x), bh1 = __float_as_uint(bb.y);
                uint32_t bl0 = __float_as_uint(bb.z), bl1 = __float_as_uint(bb.w);
#pragma unroll
                for (int mi = 0; mi < 2; mi++) {
                    mma8(acc[mi][ni], ah[mi], bh0, bh1);
                    mma8(acc[mi][ni], al[mi], bh0, bh1);
                    mma8(acc[mi][ni], ah[mi], bl0, bl1);
                }
            }
        }
        __syncthreads();   // all sH reads done; reuse buffer as sG

        // write hg tile to sG [32][96]
#pragma unroll
        for (int mi = 0; mi < 2; mi++) {
#pragma unroll
            for (int ni = 0; ni < 2; ni++) {
                int col = w * 16 + ni * 8 + 2 * cc;
                *(float2*)&sG[(mi * 16 + r) * 96 + col] =
                    make_float2(acc[mi][ni][0], acc[mi][ni][1]);
                *(float2*)&sG[(mi * 16 + r + 8) * 96 + col] =
                    make_float2(acc[mi][ni][2], acc[mi][ni][3]);
            }
        }
        __syncthreads();

        // fused GRU nonlinearity
        const float* xgrow = xg + ((size_t)t * BSZ + b0) * GV + C0;
        for (int idx = tid; idx < 1024; idx += 192) {
            int b = idx >> 5, j = idx & 31;
            const float* xp = xgrow + (size_t)b * GV;
            float xr = xp[j], xz = xp[32 + j], xn = xp[64 + j];
            float hr = sG[b * 96 + j]      + sbh[j];
            float hz = sG[b * 96 + 32 + j] + sbh[32 + j];
            float hn = sG[b * 96 + 64 + j] + sbh[64 + j];
            float rg = 1.0f / (1.0f + expf(-(xr + hr)));
            float zg = 1.0f / (1.0f + expf(-(xz + hz)));
            float ng = tanhf(xn + rg * hn);
            float hold = hc[(size_t)(b0 + b) * HV + j0 + j];
            float hv = (1.0f - zg) * ng + zg * hold;
            hnx[(size_t)(b0 + b) * HV + j0 + j] = hv;
            recOut[((size_t)(b0 + b) * TLEN + t) * H2V + dir * HV + j0 + j] = hv;
        }
        grid_barrier();
        cur ^= 1;
    }
}

// ---------------- attention + output ----------------
__global__ void __launch_bounds__(256) attention_kernel(const float* __restrict__ rec2,
                                                        float* __restrict__ out) {
    __shared__ float smerged[512];
    __shared__ float sc[256];
    __shared__ float red[8];
    __shared__ float bcast;
    int b = blockIdx.x, tid = threadIdx.x;
    const float* base = rec2 + (size_t)b * (TLEN * H2V);

    smerged[tid]       = base[255 * H2V + tid];
    smerged[256 + tid] = base[256 + tid];
    __syncthreads();

    int lane = tid & 31, wid = tid >> 5;
    for (int t = wid; t < TLEN; t += 8) {
        const float* row = base + (size_t)t * H2V;
        float s = 0.0f;
        for (int h = lane; h < H2V; h += 32) s += row[h] * smerged[h];
#pragma unroll
        for (int o = 16; o; o >>= 1) s += __shfl_xor_sync(0xffffffffu, s, o);
        if (lane == 0) sc[t] = s;
    }
    __syncthreads();

    float v = sc[tid];
    float m = v;
#pragma unroll
    for (int o = 16; o; o >>= 1) m = fmaxf(m, __shfl_xor_sync(0xffffffffu, m, o));
    if (lane == 0) red[wid] = m;
    __syncthreads();
    if (tid == 0) {
        float mm = red[0];
        for (int i = 1; i < 8; i++) mm = fmaxf(mm, red[i]);
        bcast = mm;
    }
    __syncthreads();
    m = bcast;
    float e = expf(v - m);
    float s = e;
#pragma unroll
    for (int o = 16; o; o >>= 1) s += __shfl_xor_sync(0xffffffffu, s, o);
    if (lane == 0) red[wid] = s;
    __syncthreads();
    if (tid == 0) {
        float ss = 0.0f;
        for (int i = 0; i < 8; i++) ss += red[i];
        bcast = ss;
    }
    __syncthreads();
    float wgt = e / bcast;
    sc[tid] = wgt;
    __syncthreads();

    float a0 = 0.0f, a1 = 0.0f;
    for (int t = 0; t < TLEN; t++) {
        float wt = sc[t];
        a0 += wt * base[(size_t)t * H2V + tid];
        a1 += wt * base[(size_t)t * H2V + 256 + tid];
    }
    float* ob = out + (size_t)b * 1024;
    ob[tid]       = a0;
    ob[256 + tid] = a1;
    ob[512 + tid] = base[255 * H2V + tid];
    ob[768 + tid] = base[255 * H2V + 256 + tid];
}

// ---------------- host launcher ----------------
extern "C" void kernel_launch(void* const* d_in, const int* in_sizes, int n_in,
                              void* d_out, int out_size) {
    (void)in_sizes; (void)n_in; (void)out_size;
    const float* input = (const float*)d_in[0];
    const float* wih1f = (const float*)d_in[1];
    const float* whh1f = (const float*)d_in[2];
    const float* bih1f = (const float*)d_in[3];
    const float* bhh1f = (const float*)d_in[4];
    const float* wih1r = (const float*)d_in[5];
    const float* whh1r = (const float*)d_in[6];
    const float* bih1r = (const float*)d_in[7];
    const float* bhh1r = (const float*)d_in[8];
    const float* wih2f = (const float*)d_in[9];
    const float* whh2f = (const float*)d_in[10];
    const float* bih2f = (const float*)d_in[11];
    const float* bhh2f = (const float*)d_in[12];
    const float* wih2r = (const float*)d_in[13];
    const float* whh2r = (const float*)d_in[14];
    const float* bih2r = (const float*)d_in[15];
    const float* bhh2r = (const float*)d_in[16];

    float4 *fW1f, *fW1r, *fW2f, *fW2r, *fH1f, *fH1r, *fH2f, *fH2r;
    float *bihP, *bhhP, *xgf, *xgr, *rec1, *rec2;
    cudaGetSymbolAddress((void**)&fW1f, g_fW1f);
    cudaGetSymbolAddress((void**)&fW1r, g_fW1r);
    cudaGetSymbolAddress((void**)&fW2f, g_fW2f);
    cudaGetSymbolAddress((void**)&fW2r, g_fW2r);
    cudaGetSymbolAddress((void**)&fH1f, g_fH1f);
    cudaGetSymbolAddress((void**)&fH1r, g_fH1r);
    cudaGetSymbolAddress((void**)&fH2f, g_fH2f);
    cudaGetSymbolAddress((void**)&fH2r, g_fH2r);
    cudaGetSymbolAddress((void**)&bihP, g_bihP);
    cudaGetSymbolAddress((void**)&bhhP, g_bhhP);
    cudaGetSymbolAddress((void**)&xgf, g_xgf);
    cudaGetSymbolAddress((void**)&xgr, g_xgr);
    cudaGetSymbolAddress((void**)&rec1, g_rec1);
    cudaGetSymbolAddress((void**)&rec2, g_rec2);

    // pack weight fragments (hi/lo tf32 split) + biases
    pack_frag<<<128, 256>>>(fW1f, wih1f, NINV);
    pack_frag<<<128, 256>>>(fW1r, wih1r, NINV);
    pack_frag<<<256, 256>>>(fW2f, wih2f, H2V);
    pack_frag<<<256, 256>>>(fW2r, wih2r, H2V);
    pack_frag<<<128, 256>>>(fH1f, whh1f, HV);
    pack_frag<<<128, 256>>>(fH1r, whh1r, HV);
    pack_frag<<<128, 256>>>(fH2f, whh2f, HV);
    pack_frag<<<128, 256>>>(fH2r, whh2r, HV);
    pack_b<<<1, 768>>>(bihP + 0 * GV, bih1f);
    pack_b<<<1, 768>>>(bihP + 1 * GV, bih1r);
    pack_b<<<1, 768>>>(bihP + 2 * GV, bih2f);
    pack_b<<<1, 768>>>(bihP + 3 * GV, bih2r);
    pack_b<<<1, 768>>>(bhhP + 0 * GV, bhh1f);
    pack_b<<<1, 768>>>(bhhP + 1 * GV, bhh1r);
    pack_b<<<1, 768>>>(bhhP + 2 * GV, bhh2f);
    pack_b<<<1, 768>>>(bhhP + 3 * GV, bhh2r);

    cudaFuncSetAttribute(xg_mma<NINV>, cudaFuncAttributeMaxDynamicSharedMemorySize, XG_SMEM);
    cudaFuncSetAttribute(xg_mma<H2V>, cudaFuncAttributeMaxDynamicSharedMemorySize, XG_SMEM);
    cudaFuncSetAttribute(scan_kernel, cudaFuncAttributeMaxDynamicSharedMemorySize, SCAN_SMEM);

    // Layer 1
    xg_mma<NINV><<<dim3(12, 1024), 128, XG_SMEM>>>(input, fW1f, bihP + 0 * GV, xgf);
    xg_mma<NINV><<<dim3(12, 1024), 128, XG_SMEM>>>(input, fW1r, bihP + 1 * GV, xgr);
    zero_h<<<512, 256>>>();
    scan_kernel<<<128, 192, SCAN_SMEM>>>(fH1f, fH1r, bhhP + 0 * GV, bhhP + 1 * GV,
                                         xgf, xgr, rec1);
    // Layer 2
    xg_mma<H2V><<<dim3(12, 1024), 128, XG_SMEM>>>(rec1, fW2f, bihP + 2 * GV, xgf);
    xg_mma<H2V><<<dim3(12, 1024), 128, XG_SMEM>>>(rec1, fW2r, bihP + 3 * GV, xgr);
    zero_h<<<512, 256>>>();
    scan_kernel<<<128, 192, SCAN_SMEM>>>(fH2f, fH2r, bhhP + 2 * GV, bhhP + 3 * GV,
                                         xgf, xgr, rec2);
    // Attention + output
    attention_kernel<<<256, 256>>>(rec2, (float*)d_out);
}

// round 8
// speedup vs baseline: 2.1611x; 1.7786x over previous
#include <cuda_runtime.h>
#include <math.h>
#include <stdint.h>

#define BSZ  256
#define TLEN 256
#define NINV 128
#define HV   256
#define GV   768   // 3H
#define H2V  512   // 2H

// ---------------- device scratch ----------------
// Weight fragments: [96 ntiles][K/16 ksteps][32 lanes] uint4 {bh0,bh1,bl0,bl1} (bf16x2 words)
__device__ uint4 g_fW1f[96 * 8 * 32];     // wih L1, Din=128
__device__ uint4 g_fW1r[96 * 8 * 32];
__device__ uint4 g_fW2f[96 * 32 * 32];    // wih L2, Din=512
__device__ uint4 g_fW2r[96 * 32 * 32];
__device__ uint4 g_fH1f[96 * 16 * 32];    // whh, Din=256
__device__ uint4 g_fH1r[96 * 16 * 32];
__device__ uint4 g_fH2f[96 * 16 * 32];
__device__ uint4 g_fH2r[96 * 16 * 32];
__device__ float g_bihP[4][GV];
__device__ float g_bhhP[4][GV];
__device__ float g_xgf[(size_t)TLEN * BSZ * GV];
__device__ float g_xgr[(size_t)TLEN * BSZ * GV];
__device__ uint32_t g_xinhi[(size_t)BSZ * TLEN * (NINV / 2)];   // input pre-split
__device__ uint32_t g_xinlo[(size_t)BSZ * TLEN * (NINV / 2)];
__device__ uint32_t g_r1hi[(size_t)BSZ * TLEN * (H2V / 2)];     // rec1 split (no fp32 rec1)
__device__ uint32_t g_r1lo[(size_t)BSZ * TLEN * (H2V / 2)];
__device__ float g_rec2[(size_t)BSZ * TLEN * H2V];
__device__ float g_h[2][2][BSZ * HV];                            // fp32 h (for h_old)
__device__ uint32_t g_hshi[2][2][BSZ * (HV / 2)];                // split h (MMA A input)
__device__ uint32_t g_hslo[2][2][BSZ * (HV / 2)];
__device__ unsigned g_cnt;
__device__ volatile unsigned g_gen;

// Packed column c = jt*96 + gate*32 + jl  <->  orig row = gate*256 + jt*32 + jl
__device__ __forceinline__ int orig_row(int c) {
    int g = (c % 96) >> 5;
    int jt = c / 96;
    int jl = c & 31;
    return g * HV + jt * 32 + jl;
}

// ---------------- bf16 helpers ----------------
__device__ __forceinline__ uint16_t bf16_rn(float x) {
    uint16_t u;
    asm("cvt.rn.bf16.f32 %0, %1;" : "=h"(u) : "f"(x));
    return u;
}
__device__ __forceinline__ void split2pack(float a, float b, uint32_t& hw, uint32_t& lw) {
    uint16_t ha = bf16_rn(a);
    float hfa = __uint_as_float((uint32_t)ha << 16);
    uint16_t la = bf16_rn(a - hfa);
    uint16_t hb = bf16_rn(b);
    float hfb = __uint_as_float((uint32_t)hb << 16);
    uint16_t lb = bf16_rn(b - hfb);
    hw = (uint32_t)ha | ((uint32_t)hb << 16);
    lw = (uint32_t)la | ((uint32_t)lb << 16);
}
__device__ __forceinline__ uint32_t smem_u32(const void* p) {
    return (uint32_t)__cvta_generic_to_shared(p);
}
__device__ __forceinline__ void ldm4(uint32_t* a, uint32_t addr) {
    asm volatile("ldmatrix.sync.aligned.m8n8.x4.shared.b16 {%0,%1,%2,%3}, [%4];"
                 : "=r"(a[0]), "=r"(a[1]), "=r"(a[2]), "=r"(a[3]) : "r"(addr));
}
__device__ __forceinline__ void mma16(float* c, const uint32_t* a, uint32_t b0, uint32_t b1) {
    asm volatile("mma.sync.aligned.m16n8k16.row.col.f32.bf16.bf16.f32 "
                 "{%0,%1,%2,%3},{%4,%5,%6,%7},{%8,%9},{%0,%1,%2,%3};"
                 : "+f"(c[0]), "+f"(c[1]), "+f"(c[2]), "+f"(c[3])
                 : "r"(a[0]), "r"(a[1]), "r"(a[2]), "r"(a[3]), "r"(b0), "r"(b1));
}
__device__ __forceinline__ float sigm(float x) {
    float e = __expf(-x);
    return __fdividef(1.0f, 1.0f + e);
}

// ---------------- packing ----------------
// b0 reg = {B[k=2t][n] lo, B[k=2t+1][n] hi}; b1 = k+8 pair. B[k][c] = W[orig_row(c)][k].
__global__ void pack_frag(uint4* __restrict__ dst, const float* __restrict__ src, int Din) {
    int KS = Din >> 4;
    int tot = 96 * KS * 32;
    for (int idx = blockIdx.x * blockDim.x + threadIdx.x; idx < tot;
         idx += gridDim.x * blockDim.x) {
        int lane = idx & 31;
        int ks = (idx >> 5) % KS;
        int nt = idx / (32 * KS);
        int cg = nt * 8 + (lane >> 2);
        int r = orig_row(cg);
        int k0 = ks * 16 + (lane & 3) * 2;
        const float* s = src + (size_t)r * Din;
        uint32_t bh0, bl0, bh1, bl1;
        split2pack(s[k0], s[k0 + 1], bh0, bl0);
        split2pack(s[k0 + 8], s[k0 + 9], bh1, bl1);
        dst[idx] = make_uint4(bh0, bh1, bl0, bl1);
    }
}

__global__ void pack_b(float* __restrict__ dst, const float* __restrict__ src) {
    int c = threadIdx.x;
    if (c < GV) dst[c] = src[orig_row(c)];
}

__global__ void zero_h() {
    int idx = blockIdx.x * blockDim.x + threadIdx.x;
    int stride = gridDim.x * blockDim.x;
    for (int i = idx; i < 2 * BSZ * HV; i += stride) ((float*)g_h)[i] = 0.0f;
    for (int i = idx; i < 2 * BSZ * (HV / 2); i += stride) {
        ((uint32_t*)g_hshi)[i] = 0u;
        ((uint32_t*)g_hslo)[i] = 0u;
    }
}

// input [rows][K] fp32 -> packed bf16 hi/lo words
__global__ void split_input(const float* __restrict__ src, uint32_t* __restrict__ hi,
                            uint32_t* __restrict__ lo, int words) {
    for (int idx = blockIdx.x * blockDim.x + threadIdx.x; idx < words;
         idx += gridDim.x * blockDim.x) {
        float2 v = *(const float2*)&src[(size_t)idx * 2];
        uint32_t hw, lw;
        split2pack(v.x, v.y, hw, lw);
        hi[idx] = hw;
        lo[idx] = lw;
    }
}

// ---------------- input-gate GEMM (bf16x3 mma.sync) ----------------
// A pre-split packed words, row stride KW = K/2. CTA tile 64x64, 4 warps, k-chunk 64.
#define XG_SMEM (9216 + 9216 + 16384)
extern __shared__ char smem_raw[];

template <int KW>   // words per A row (K/2)
__global__ void __launch_bounds__(128) xg_mma(const uint32_t* __restrict__ Ahi,
                                              const uint32_t* __restrict__ Alo,
                                              const uint4* __restrict__ fB,
                                              const float* __restrict__ bias,
                                              float* __restrict__ out) {
    char* sAhi = smem_raw;                  // 64 rows x 144B
    char* sAlo = smem_raw + 9216;
    uint4* sB = (uint4*)(smem_raw + 18432); // [8nt][4ks][32]
    const int KSTEPS = KW >> 3;             // K/16

    int tid = threadIdx.x;
    int w = tid >> 5, lane = tid & 31;
    int m0 = blockIdx.y * 64;
    int n0blk = blockIdx.x * 8;
    int wm = (w & 1) * 32;
    int wn = (w >> 1) * 4;
    int r = lane >> 2, cc = lane & 3;

    int rl = lane & 15, kh = (lane >> 4) * 16;
    uint32_t aH0 = smem_u32(sAhi) + (wm + rl) * 144 + kh;
    uint32_t aH1 = aH0 + 16 * 144;
    uint32_t aL0 = smem_u32(sAlo) + (wm + rl) * 144 + kh;
    uint32_t aL1 = aL0 + 16 * 144;

    float acc[2][4][4] = {};

    for (int ch = 0; ch < KW / 32; ch++) {
        int kcW = ch * 32;
        __syncthreads();
        for (int idx = tid; idx < 512; idx += 128) {
            int row = idx >> 3, q = idx & 7;
            const uint4* shv = (const uint4*)&Ahi[(size_t)(m0 + row) * KW + kcW + q * 4];
            const uint4* slv = (const uint4*)&Alo[(size_t)(m0 + row) * KW + kcW + q * 4];
            *(uint4*)(sAhi + row * 144 + q * 16) = *shv;
            *(uint4*)(sAlo + row * 144 + q * 16) = *slv;
        }
        for (int idx = tid; idx < 1024; idx += 128) {
            int nt = idx >> 7, ks = (idx >> 5) & 3, ln = idx & 31;
            sB[idx] = fB[((size_t)(n0blk + nt) * KSTEPS + ch * 4 + ks) * 32 + ln];
        }
        __syncthreads();
#pragma unroll
        for (int ks = 0; ks < 4; ks++) {
            uint32_t ah0[4], ah1[4], al0[4], al1[4];
            ldm4(ah0, aH0 + ks * 32);
            ldm4(ah1, aH1 + ks * 32);
            ldm4(al0, aL0 + ks * 32);
            ldm4(al1, aL1 + ks * 32);
#pragma unroll
            for (int ni = 0; ni < 4; ni++) {
                uint4 bb = sB[((wn + ni) * 4 + ks) * 32 + lane];
                mma16(acc[0][ni], ah0, bb.x, bb.y);
                mma16(acc[1][ni], ah1, bb.x, bb.y);
                mma16(acc[0][ni], al0, bb.x, bb.y);
                mma16(acc[1][ni], al1, bb.x, bb.y);
                mma16(acc[0][ni], ah0, bb.z, bb.w);
                mma16(acc[1][ni], ah1, bb.z, bb.w);
            }
        }
    }
    // epilogue: row m = b*256+t -> out [t][b][GV]
#pragma unroll
    for (int mi = 0; mi < 2; mi++) {
#pragma unroll
        for (int half = 0; half < 2; half++) {
            int row = m0 + wm + mi * 16 + r + half * 8;
            int b = row >> 8, t = row & 255;
            float* orow = out + ((size_t)t * BSZ + b) * GV;
#pragma unroll
            for (int ni = 0; ni < 4; ni++) {
                int col = (n0blk + wn + ni) * 8 + 2 * cc;
                float2 bs = *(const float2*)&bias[col];
                float2 o;
                o.x = acc[mi][ni][half * 2 + 0] + bs.x;
                o.y = acc[mi][ni][half * 2 + 1] + bs.y;
                *(float2*)&orow[col] = o;
            }
        }
    }
}

// ---------------- grid barrier ----------------
__device__ __forceinline__ void grid_barrier() {
    __syncthreads();
    if (threadIdx.x == 0) {
        __threadfence();
        unsigned my = g_gen;
        unsigned t = atomicAdd(&g_cnt, 1u);
        if (t == gridDim.x - 1) {
            g_cnt = 0u;
            __threadfence();
            g_gen = my + 1u;
        } else {
            while (g_gen == my) { __nanosleep(32); }
        }
        __threadfence();
    }
    __syncthreads();
}

// ---------------- recurrent scan (bf16x3) ----------------
// 128 CTAs: dir=bid>>6, bt=(bid&63)>>3, jt=bid&7. Whh frags pinned in SMEM.
// mode 0: write rec1 split (hi/lo); mode 1: write rec2 fp32.
#define SB_BYTES (96 * 1024)            // 12nt x 16ks x 32 x 16B
#define SH_BYTES (32 * 528)             // 32 rows x 528B
#define SCAN_SMEM (SB_BYTES + 2 * SH_BYTES)   // 132096
__global__ void __launch_bounds__(192, 1) scan_kernel(const uint4* __restrict__ fWf,
                                                      const uint4* __restrict__ fWr,
                                                      const float* __restrict__ bhf,
                                                      const float* __restrict__ bhr,
                                                      const float* __restrict__ xgF,
                                                      const float* __restrict__ xgR,
                                                      float* __restrict__ recF,
                                                      uint32_t* __restrict__ recHi,
                                                      uint32_t* __restrict__ recLo,
                                                      int mode) {
    uint4* sB4 = (uint4*)smem_raw;                         // weight frags
    char* sHhi = smem_raw + SB_BYTES;
    char* sHlo = sHhi + SH_BYTES;
    float* sG = (float*)sHhi;                              // alias after MMA
    __shared__ float sbh[96];

    int tid = threadIdx.x;
    int w = tid >> 5, lane = tid & 31;
    int dir = blockIdx.x >> 6;
    int tile = blockIdx.x & 63;
    int bt = tile >> 3, jt = tile & 7;
    int b0 = bt * 32, j0 = jt * 32, C0 = jt * 96;

    const uint4* fW = dir ? fWr : fWf;
    const float* bh = dir ? bhr : bhf;
    const float* xg = dir ? xgR : xgF;

    for (int idx = tid; idx < 12 * 16 * 32; idx += 192)
        sB4[idx] = fW[(size_t)jt * (12 * 16 * 32) + idx];
    if (tid < 96) sbh[tid] = bh[C0 + tid];

    int r = lane >> 2, cc = lane & 3;
    int rl = lane & 15, kh = (lane >> 4) * 16;
    uint32_t aH0 = smem_u32(sHhi) + rl * 528 + kh;
    uint32_t aH1 = aH0 + 16 * 528;
    uint32_t aL0 = smem_u32(sHlo) + rl * 528 + kh;
    uint32_t aL1 = aL0 + 16 * 528;

    int cur = 0;
    for (int step = 0; step < TLEN; step++) {
        int t = dir ? (TLEN - 1 - step) : step;
        const float* hc = g_h[cur][dir];
        float* hnx = g_h[cur ^ 1][dir];
        const uint32_t* hsh = g_hshi[cur][dir];
        const uint32_t* hsl = g_hslo[cur][dir];
        uint32_t* hshN = g_hshi[cur ^ 1][dir];
        uint32_t* hslN = g_hslo[cur ^ 1][dir];

        // copy pre-split h tile: 32 rows x 32 uint4 (hi) + same (lo)
        for (int idx = tid; idx < 2048; idx += 192) {
            int half = idx >> 10;          // 0=hi 1=lo
            int row = (idx >> 5) & 31, q = idx & 31;
            const uint32_t* src = half ? hsl : hsh;
            uint4 v = *(const uint4*)&src[(size_t)(b0 + row) * 128 + q * 4];
            char* dst = half ? sHlo : sHhi;
            *(uint4*)(dst + row * 528 + q * 16) = v;
        }
        __syncthreads();

        float acc[2][2][4] = {};
#pragma unroll 4
        for (int ks = 0; ks < 16; ks++) {
            uint32_t ah0[4], ah1[4], al0[4], al1[4];
            ldm4(ah0, aH0 + ks * 32);
            ldm4(ah1, aH1 + ks * 32);
            ldm4(al0, aL0 + ks * 32);
            ldm4(al1, aL1 + ks * 32);
#pragma unroll
            for (int ni = 0; ni < 2; ni++) {
                uint4 bb = sB4[((2 * w + ni) * 16 + ks) * 32 + lane];
                mma16(acc[0][ni], ah0, bb.x, bb.y);
                mma16(acc[1][ni], ah1, bb.x, bb.y);
                mma16(acc[0][ni], al0, bb.x, bb.y);
                mma16(acc[1][ni], al1, bb.x, bb.y);
                mma16(acc[0][ni], ah0, bb.z, bb.w);
                mma16(acc[1][ni], ah1, bb.z, bb.w);
            }
        }
        __syncthreads();   // sH reads done; reuse as sG

#pragma unroll
        for (int mi = 0; mi < 2; mi++) {
#pragma unroll
            for (int ni = 0; ni < 2; ni++) {
                int col = w * 16 + ni * 8 + 2 * cc;
                *(float2*)&sG[(mi * 16 + r) * 96 + col] =
                    make_float2(acc[mi][ni][0], acc[mi][ni][1]);
                *(float2*)&sG[(mi * 16 + r + 8) * 96 + col] =
                    make_float2(acc[mi][ni][2], acc[mi][ni][3]);
            }
        }
        __syncthreads();

        // fused GRU nonlinearity, 2 adjacent j per thread
        const float* xgrow = xg + ((size_t)t * BSZ + b0) * GV + C0;
        for (int idx = tid; idx < 512; idx += 192) {
            int b = idx >> 4;
            int j = (idx & 15) * 2;
            const float* xp = xgrow + (size_t)b * GV;
            int row = b0 + b;
            float2 hold = *(const float2*)&hc[(size_t)row * HV + j0 + j];
            float hv[2];
#pragma unroll
            for (int u = 0; u < 2; u++) {
                int jj = j + u;
                float xr = xp[jj], xz = xp[32 + jj], xn = xp[64 + jj];
                float hr = sG[b * 96 + jj] + sbh[jj];
                float hz = sG[b * 96 + 32 + jj] + sbh[32 + jj];
                float hn = sG[b * 96 + 64 + jj] + sbh[64 + jj];
                float rg = sigm(xr + hr);
                float zg = sigm(xz + hz);
                float ng = 2.0f * sigm(2.0f * (xn + rg * hn)) - 1.0f;
                float ho = u ? hold.y : hold.x;
                hv[u] = (1.0f - zg) * ng + zg * ho;
            }
            *(float2*)&hnx[(size_t)row * HV + j0 + j] = make_float2(hv[0], hv[1]);
            uint32_t hw, lw;
            split2pack(hv[0], hv[1], hw, lw);
            int wj = (j0 + j) >> 1;
            hshN[(size_t)row * 128 + wj] = hw;
            hslN[(size_t)row * 128 + wj] = lw;
            if (mode) {
                *(float2*)&recF[((size_t)row * TLEN + t) * H2V + dir * HV + j0 + j] =
                    make_float2(hv[0], hv[1]);
            } else {
                size_t o = ((size_t)row * TLEN + t) * 256 + dir * 128 + wj;
                recHi[o] = hw;
                recLo[o] = lw;
            }
        }
        grid_barrier();
        cur ^= 1;
    }
}

// ---------------- attention + output ----------------
__global__ void __launch_bounds__(256) attention_kernel(const float* __restrict__ rec2,
                                                        float* __restrict__ out) {
    __shared__ float smerged[512];
    __shared__ float sc[256];
    __shared__ float red[8];
    __shared__ float bcast;
    int b = blockIdx.x, tid = threadIdx.x;
    const float* base = rec2 + (size_t)b * (TLEN * H2V);

    smerged[tid] = base[255 * H2V + tid];
    smerged[256 + tid] = base[256 + tid];
    __syncthreads();

    int lane = tid & 31, wid = tid >> 5;
    for (int t = wid; t < TLEN; t += 8) {
        const float* row = base + (size_t)t * H2V;
        float s = 0.0f;
        for (int h = lane; h < H2V; h += 32) s += row[h] * smerged[h];
#pragma unroll
        for (int o = 16; o; o >>= 1) s += __shfl_xor_sync(0xffffffffu, s, o);
        if (lane == 0) sc[t] = s;
    }
    __syncthreads();

    float v = sc[tid];
    float m = v;
#pragma unroll
    for (int o = 16; o; o >>= 1) m = fmaxf(m, __shfl_xor_sync(0xffffffffu, m, o));
    if (lane == 0) red[wid] = m;
    __syncthreads();
    if (tid == 0) {
        float mm = red[0];
        for (int i = 1; i < 8; i++) mm = fmaxf(mm, red[i]);
        bcast = mm;
    }
    __syncthreads();
    m = bcast;
    float e = expf(v - m);
    float s = e;
#pragma unroll
    for (int o = 16; o; o >>= 1) s += __shfl_xor_sync(0xffffffffu, s, o);
    if (lane == 0) red[wid] = s;
    __syncthreads();
    if (tid == 0) {
        float ss = 0.0f;
        for (int i = 0; i < 8; i++) ss += red[i];
        bcast = ss;
    }
    __syncthreads();
    float wgt = e / bcast;
    sc[tid] = wgt;
    __syncthreads();

    float a0 = 0.0f, a1 = 0.0f;
    for (int t = 0; t < TLEN; t++) {
        float wt = sc[t];
        a0 += wt * base[(size_t)t * H2V + tid];
        a1 += wt * base[(size_t)t * H2V + 256 + tid];
    }
    float* ob = out + (size_t)b * 1024;
    ob[tid] = a0;
    ob[256 + tid] = a1;
    ob[512 + tid] = base[255 * H2V + tid];
    ob[768 + tid] = base[255 * H2V + 256 + tid];
}

// ---------------- host launcher ----------------
extern "C" void kernel_launch(void* const* d_in, const int* in_sizes, int n_in,
                              void* d_out, int out_size) {
    (void)in_sizes; (void)n_in; (void)out_size;
    const float* input = (const float*)d_in[0];
    const float* wih1f = (const float*)d_in[1];
    const float* whh1f = (const float*)d_in[2];
    const float* bih1f = (const float*)d_in[3];
    const float* bhh1f = (const float*)d_in[4];
    const float* wih1r = (const float*)d_in[5];
    const float* whh1r = (const float*)d_in[6];
    const float* bih1r = (const float*)d_in[7];
    const float* bhh1r = (const float*)d_in[8];
    const float* wih2f = (const float*)d_in[9];
    const float* whh2f = (const float*)d_in[10];
    const float* bih2f = (const float*)d_in[11];
    const float* bhh2f = (const float*)d_in[12];
    const float* wih2r = (const float*)d_in[13];
    const float* whh2r = (const float*)d_in[14];
    const float* bih2r = (const float*)d_in[15];
    const float* bhh2r = (const float*)d_in[16];

    uint4 *fW1f, *fW1r, *fW2f, *fW2r, *fH1f, *fH1r, *fH2f, *fH2r;
    float *bihP, *bhhP, *xgf, *xgr, *rec2;
    uint32_t *xinhi, *xinlo, *r1hi, *r1lo;
    cudaGetSymbolAddress((void**)&fW1f, g_fW1f);
    cudaGetSymbolAddress((void**)&fW1r, g_fW1r);
    cudaGetSymbolAddress((void**)&fW2f, g_fW2f);
    cudaGetSymbolAddress((void**)&fW2r, g_fW2r);
    cudaGetSymbolAddress((void**)&fH1f, g_fH1f);
    cudaGetSymbolAddress((void**)&fH1r, g_fH1r);
    cudaGetSymbolAddress((void**)&fH2f, g_fH2f);
    cudaGetSymbolAddress((void**)&fH2r, g_fH2r);
    cudaGetSymbolAddress((void**)&bihP, g_bihP);
    cudaGetSymbolAddress((void**)&bhhP, g_bhhP);
    cudaGetSymbolAddress((void**)&xgf, g_xgf);
    cudaGetSymbolAddress((void**)&xgr, g_xgr);
    cudaGetSymbolAddress((void**)&rec2, g_rec2);
    cudaGetSymbolAddress((void**)&xinhi, g_xinhi);
    cudaGetSymbolAddress((void**)&xinlo, g_xinlo);
    cudaGetSymbolAddress((void**)&r1hi, g_r1hi);
    cudaGetSymbolAddress((void**)&r1lo, g_r1lo);

    split_input<<<2048, 256>>>(input, xinhi, xinlo, BSZ * TLEN * (NINV / 2));
    pack_frag<<<96, 256>>>(fW1f, wih1f, NINV);
    pack_frag<<<96, 256>>>(fW1r, wih1r, NINV);
    pack_frag<<<192, 256>>>(fW2f, wih2f, H2V);
    pack_frag<<<192, 256>>>(fW2r, wih2r, H2V);
    pack_frag<<<128, 256>>>(fH1f, whh1f, HV);
    pack_frag<<<128, 256>>>(fH1r, whh1r, HV);
    pack_frag<<<128, 256>>>(fH2f, whh2f, HV);
    pack_frag<<<128, 256>>>(fH2r, whh2r, HV);
    pack_b<<<1, 768>>>(bihP + 0 * GV, bih1f);
    pack_b<<<1, 768>>>(bihP + 1 * GV, bih1r);
    pack_b<<<1, 768>>>(bihP + 2 * GV, bih2f);
    pack_b<<<1, 768>>>(bihP + 3 * GV, bih2r);
    pack_b<<<1, 768>>>(bhhP + 0 * GV, bhh1f);
    pack_b<<<1, 768>>>(bhhP + 1 * GV, bhh1r);
    pack_b<<<1, 768>>>(bhhP + 2 * GV, bhh2f);
    pack_b<<<1, 768>>>(bhhP + 3 * GV, bhh2r);

    cudaFuncSetAttribute(xg_mma<64>, cudaFuncAttributeMaxDynamicSharedMemorySize, XG_SMEM);
    cudaFuncSetAttribute(xg_mma<256>, cudaFuncAttributeMaxDynamicSharedMemorySize, XG_SMEM);
    cudaFuncSetAttribute(scan_kernel, cudaFuncAttributeMaxDynamicSharedMemorySize, SCAN_SMEM);

    // Layer 1
    xg_mma<64><<<dim3(12, 1024), 128, XG_SMEM>>>(xinhi, xinlo, fW1f, bihP + 0 * GV, xgf);
    xg_mma<64><<<dim3(12, 1024), 128, XG_SMEM>>>(xinhi, xinlo, fW1r, bihP + 1 * GV, xgr);
    zero_h<<<256, 256>>>();
    scan_kernel<<<128, 192, SCAN_SMEM>>>(fH1f, fH1r, bhhP + 0 * GV, bhhP + 1 * GV,
                                         xgf, xgr, nullptr, r1hi, r1lo, 0);
    // Layer 2
    xg_mma<256><<<dim3(12, 1024), 128, XG_SMEM>>>(r1hi, r1lo, fW2f, bihP + 2 * GV, xgf);
    xg_mma<256><<<dim3(12, 1024), 128, XG_SMEM>>>(r1hi, r1lo, fW2r, bihP + 3 * GV, xgr);
    zero_h<<<256, 256>>>();
    scan_kernel<<<128, 192, SCAN_SMEM>>>(fH2f, fH2r, bhhP + 2 * GV, bhhP + 3 * GV,
                                         xgf, xgr, rec2, nullptr, nullptr, 1);
    // Attention + output
    attention_kernel<<<256, 256>>>(rec2, (float*)d_out);
}

// round 11
// speedup vs baseline: 2.3813x; 1.1019x over previous
#include <cuda_runtime.h>
#include <math.h>
#include <stdint.h>

#define BSZ  256
#define TLEN 256
#define NINV 128
#define HV   256
#define GV   768   // 3H
#define H2V  512   // 2H

// ---------------- device scratch ----------------
// Weight fragments: [96 ntiles][K/16 ksteps][32 lanes] uint4 {bh0,bh1,bl0,bl1}
__device__ uint4 g_fW1f[96 * 8 * 32];     // wih L1, Din=128
__device__ uint4 g_fW1r[96 * 8 * 32];
__device__ uint4 g_fW2f[96 * 32 * 32];    // wih L2, Din=512
__device__ uint4 g_fW2r[96 * 32 * 32];
__device__ uint4 g_fH1f[96 * 16 * 32];    // whh, Din=256
__device__ uint4 g_fH1r[96 * 16 * 32];
__device__ uint4 g_fH2f[96 * 16 * 32];
__device__ uint4 g_fH2r[96 * 16 * 32];
__device__ float g_bihP[4][GV];
__device__ float g_bhhP[4][GV];
__device__ float g_xgf[(size_t)TLEN * BSZ * GV];
__device__ float g_xgr[(size_t)TLEN * BSZ * GV];
__device__ uint32_t g_xinhi[(size_t)BSZ * TLEN * (NINV / 2)];
__device__ uint32_t g_xinlo[(size_t)BSZ * TLEN * (NINV / 2)];
__device__ uint32_t g_r1hi[(size_t)BSZ * TLEN * (H2V / 2)];
__device__ uint32_t g_r1lo[(size_t)BSZ * TLEN * (H2V / 2)];
__device__ float g_rec2[(size_t)BSZ * TLEN * H2V];
__device__ float g_h[2][2][BSZ * HV];
__device__ uint32_t g_hshi[2][2][BSZ * (HV / 2)];
__device__ uint32_t g_hslo[2][2][BSZ * (HV / 2)];
// 16 group barriers (dir*8+bt), padded to 128B each to avoid sector contention
__device__ unsigned g_gcnt[16 * 32];
__device__ volatile unsigned g_ggen[16 * 32];

// Packed column c = jt*96 + gate*32 + jl  <->  orig row = gate*256 + jt*32 + jl
__device__ __forceinline__ int orig_row(int c) {
    int g = (c % 96) >> 5;
    int jt = c / 96;
    int jl = c & 31;
    return g * HV + jt * 32 + jl;
}

// ---------------- bf16 helpers ----------------
__device__ __forceinline__ uint16_t bf16_rn(float x) {
    uint16_t u;
    asm("cvt.rn.bf16.f32 %0, %1;" : "=h"(u) : "f"(x));
    return u;
}
__device__ __forceinline__ void split2pack(float a, float b, uint32_t& hw, uint32_t& lw) {
    uint16_t ha = bf16_rn(a);
    float hfa = __uint_as_float((uint32_t)ha << 16);
    uint16_t la = bf16_rn(a - hfa);
    uint16_t hb = bf16_rn(b);
    float hfb = __uint_as_float((uint32_t)hb << 16);
    uint16_t lb = bf16_rn(b - hfb);
    hw = (uint32_t)ha | ((uint32_t)hb << 16);
    lw = (uint32_t)la | ((uint32_t)lb << 16);
}
__device__ __forceinline__ uint32_t smem_u32(const void* p) {
    return (uint32_t)__cvta_generic_to_shared(p);
}
__device__ __forceinline__ void ldm4(uint32_t* a, uint32_t addr) {
    asm volatile("ldmatrix.sync.aligned.m8n8.x4.shared.b16 {%0,%1,%2,%3}, [%4];"
                 : "=r"(a[0]), "=r"(a[1]), "=r"(a[2]), "=r"(a[3]) : "r"(addr));
}
__device__ __forceinline__ void mma16(float* c, const uint32_t* a, uint32_t b0, uint32_t b1) {
    asm volatile("mma.sync.aligned.m16n8k16.row.col.f32.bf16.bf16.f32 "
                 "{%0,%1,%2,%3},{%4,%5,%6,%7},{%8,%9},{%0,%1,%2,%3};"
                 : "+f"(c[0]), "+f"(c[1]), "+f"(c[2]), "+f"(c[3])
                 : "r"(a[0]), "r"(a[1]), "r"(a[2]), "r"(a[3]), "r"(b0), "r"(b1));
}
__device__ __forceinline__ float sigm(float x) {
    float e = __expf(-x);
    return __fdividef(1.0f, 1.0f + e);
}
__device__ __forceinline__ void cpa16(uint32_t dst, const void* src) {
    asm volatile("cp.async.cg.shared.global [%0], [%1], 16;" :: "r"(dst), "l"(src));
}
#define CP_COMMIT() asm volatile("cp.async.commit_group;" ::: "memory")
#define CP_WAIT0()  asm volatile("cp.async.wait_group 0;" ::: "memory")
#define CP_WAIT1()  asm volatile("cp.async.wait_group 1;" ::: "memory")

// ---------------- packing ----------------
__global__ void pack_frag(uint4* __restrict__ dst, const float* __restrict__ src, int Din) {
    int KS = Din >> 4;
    int tot = 96 * KS * 32;
    for (int idx = blockIdx.x * blockDim.x + threadIdx.x; idx < tot;
         idx += gridDim.x * blockDim.x) {
        int lane = idx & 31;
        int ks = (idx >> 5) % KS;
        int nt = idx / (32 * KS);
        int cg = nt * 8 + (lane >> 2);
        int r = orig_row(cg);
        int k0 = ks * 16 + (lane & 3) * 2;
        const float* s = src + (size_t)r * Din;
        uint32_t bh0, bl0, bh1, bl1;
        split2pack(s[k0], s[k0 + 1], bh0, bl0);
        split2pack(s[k0 + 8], s[k0 + 9], bh1, bl1);
        dst[idx] = make_uint4(bh0, bh1, bl0, bl1);
    }
}

__global__ void pack_b(float* __restrict__ dst, const float* __restrict__ src) {
    int c = threadIdx.x;
    if (c < GV) dst[c] = src[orig_row(c)];
}

__global__ void zero_h() {
    int idx = blockIdx.x * blockDim.x + threadIdx.x;
    int stride = gridDim.x * blockDim.x;
    for (int i = idx; i < 2 * BSZ * HV; i += stride) ((float*)g_h)[i] = 0.0f;
    for (int i = idx; i < 2 * BSZ * (HV / 2); i += stride) {
        ((uint32_t*)g_hshi)[i] = 0u;
        ((uint32_t*)g_hslo)[i] = 0u;
    }
}

__global__ void split_input(const float* __restrict__ src, uint32_t* __restrict__ hi,
                            uint32_t* __restrict__ lo, int words) {
    for (int idx = blockIdx.x * blockDim.x + threadIdx.x; idx < words;
         idx += gridDim.x * blockDim.x) {
        float2 v = *(const float2*)&src[(size_t)idx * 2];
        uint32_t hw, lw;
        split2pack(v.x, v.y, hw, lw);
        hi[idx] = hw;
        lo[idx] = lw;
    }
}

// ---------------- input-gate GEMM (bf16x3, cp.async double-buffered) ----------------
// Stage: Ahi 64x144B (9216) + Alo (9216) + B 16384 = 34816; two stages.
#define XG_STAGE 34816
#define XG_SMEM (2 * XG_STAGE)
extern __shared__ char smem_raw[];

template <int KW>
__device__ __forceinline__ void xg_issue(uint32_t st, int tid, int m0, int n0blk, int ch,
                                         const uint32_t* __restrict__ Ahi,
                                         const uint32_t* __restrict__ Alo,
                                         const uint4* __restrict__ fB) {
    const int KSTEPS = KW >> 3;
    int kc = ch * 32;
    for (int idx = tid; idx < 2048; idx += 128) {
        if (idx < 512) {
            int row = idx >> 3, q = idx & 7;
            cpa16(st + row * 144 + q * 16, &Ahi[(size_t)(m0 + row) * KW + kc + q * 4]);
        } else if (idx < 1024) {
            int e = idx - 512, row = e >> 3, q = e & 7;
            cpa16(st + 9216 + row * 144 + q * 16, &Alo[(size_t)(m0 + row) * KW + kc + q * 4]);
        } else {
            int e = idx - 1024;
            int nt = e >> 7, ks = (e >> 5) & 3, ln = e & 31;
            cpa16(st + 18432 + e * 16,
                  &fB[((size_t)(n0blk + nt) * KSTEPS + ch * 4 + ks) * 32 + ln]);
        }
    }
    CP_COMMIT();
}

template <int KW>   // words per A row (K/2)
__global__ void __launch_bounds__(128) xg_mma(const uint32_t* __restrict__ Ahi,
                                              const uint32_t* __restrict__ Alo,
                                              const uint4* __restrict__ fB,
                                              const float* __restrict__ bias,
                                              float* __restrict__ out) {
    const int NC = KW / 32;              // 64-element k-chunks
    uint32_t sb = smem_u32(smem_raw);
    int tid = threadIdx.x;
    int w = tid >> 5, lane = tid & 31;
    int m0 = blockIdx.y * 64;
    int n0blk = blockIdx.x * 8;
    int wm = (w & 1) * 32;
    int wn = (w >> 1) * 4;
    int r = lane >> 2, cc = lane & 3;
    int rl = lane & 15, kh = (lane >> 4) * 16;

    xg_issue<KW>(sb, tid, m0, n0blk, 0, Ahi, Alo, fB);

    float acc[2][4][4] = {};
    for (int ch = 0; ch < NC; ch++) {
        int s = ch & 1;
        if (ch + 1 < NC) {
            xg_issue<KW>(sb + (s ^ 1) * XG_STAGE, tid, m0, n0blk, ch + 1, Ahi, Alo, fB);
            CP_WAIT1();
        } else {
            CP_WAIT0();
        }
        __syncthreads();
        uint32_t stg = sb + s * XG_STAGE;
        uint32_t aH0 = stg + (wm + rl) * 144 + kh;
        uint32_t aH1 = aH0 + 16 * 144;
        uint32_t aL0 = aH0 + 9216;
        uint32_t aL1 = aL0 + 16 * 144;
        const uint4* sB = (const uint4*)(smem_raw + s * XG_STAGE + 18432);
#pragma unroll
        for (int ks = 0; ks < 4; ks++) {
            uint32_t ah0[4], ah1[4], al0[4], al1[4];
            ldm4(ah0, aH0 + ks * 32);
            ldm4(ah1, aH1 + ks * 32);
            ldm4(al0, aL0 + ks * 32);
            ldm4(al1, aL1 + ks * 32);
#pragma unroll
            for (int ni = 0; ni < 4; ni++) {
                uint4 bb = sB[((wn + ni) * 4 + ks) * 32 + lane];
                mma16(acc[0][ni], ah0, bb.x, bb.y);
                mma16(acc[1][ni], ah1, bb.x, bb.y);
                mma16(acc[0][ni], al0, bb.x, bb.y);
                mma16(acc[1][ni], al1, bb.x, bb.y);
                mma16(acc[0][ni], ah0, bb.z, bb.w);
                mma16(acc[1][ni], ah1, bb.z, bb.w);
            }
        }
        __syncthreads();   // all warps done reading stage s before it is refilled
    }
    // epilogue: row m = b*256+t -> out [t][b][GV]
#pragma unroll
    for (int mi = 0; mi < 2; mi++) {
#pragma unroll
        for (int half = 0; half < 2; half++) {
            int row = m0 + wm + mi * 16 + r + half * 8;
            int b = row >> 8, t = row & 255;
            float* orow = out + ((size_t)t * BSZ + b) * GV;
#pragma unroll
            for (int ni = 0; ni < 4; ni++) {
                int col = (n0blk + wn + ni) * 8 + 2 * cc;
                float2 bs = *(const float2*)&bias[col];
                float2 o;
                o.x = acc[mi][ni][half * 2 + 0] + bs.x;
                o.y = acc[mi][ni][half * 2 + 1] + bs.y;
                *(float2*)&orow[col] = o;
            }
        }
    }
}

// ---------------- group barrier (8 CTAs sharing (dir,bt)) ----------------
__device__ __forceinline__ void group_barrier(int grp) {
    __syncthreads();
    if (threadIdx.x == 0) {
        __threadfence();
        unsigned my = g_ggen[grp * 32];
        unsigned t = atomicAdd(&g_gcnt[grp * 32], 1u);
        if (t == 7u) {
            g_gcnt[grp * 32] = 0u;
            __threadfence();
            g_ggen[grp * 32] = my + 1u;
        } else {
            while (g_ggen[grp * 32] == my) { __nanosleep(20); }
        }
        __threadfence();
    }
    __syncthreads();
}

// ---------------- recurrent scan (bf16x3, 8 warps, group barriers) ----------------
#define SB_BYTES (96 * 1024)
#define SH_BYTES (32 * 528)
#define SCAN_SMEM (SB_BYTES + 2 * SH_BYTES)
__global__ void __launch_bounds__(256, 1) scan_kernel(const uint4* __restrict__ fWf,
                                                      const uint4* __restrict__ fWr,
                                                      const float* __restrict__ bhf,
                                                      const float* __restrict__ bhr,
                                                      const float* __restrict__ xgF,
                                                      const float* __restrict__ xgR,
                                                      float* __restrict__ recF,
                                                      uint32_t* __restrict__ recHi,
                                                      uint32_t* __restrict__ recLo,
                                                      int mode) {
    uint4* sB4 = (uint4*)smem_raw;
    char* sHhi = smem_raw + SB_BYTES;
    char* sHlo = sHhi + SH_BYTES;
    float* sG = (float*)sHhi;
    __shared__ float sbh[96];

    int tid = threadIdx.x;
    int w = tid >> 5, lane = tid & 31;
    int dir = blockIdx.x >> 6;
    int tile = blockIdx.x & 63;
    int bt = tile >> 3, jt = tile & 7;
    int b0 = bt * 32, j0 = jt * 32, C0 = jt * 96;
    int grp = (int)(blockIdx.x >> 3);    // dir*8 + bt

    const uint4* fW = dir ? fWr : fWf;
    const float* bh = dir ? bhr : bhf;
    const float* xg = dir ? xgR : xgF;

    for (int idx = tid; idx < 12 * 16 * 32; idx += 256)
        sB4[idx] = fW[(size_t)jt * (12 * 16 * 32) + idx];
    if (tid < 96) sbh[tid] = bh[C0 + tid];

    // warp layout: 2 m-tiles x 4 n-groups (3 ntiles = 24 cols each)
    int wx = w & 3, my = (w >> 2) * 16;
    int nb = wx * 3;
    int r = lane >> 2, cc = lane & 3;
    int rl = lane & 15, kh = (lane >> 4) * 16;
    uint32_t aH0 = smem_u32(sHhi) + (my + rl) * 528 + kh;
    uint32_t aL0 = smem_u32(sHlo) + (my + rl) * 528 + kh;

    int cur = 0;
    for (int step = 0; step < TLEN; step++) {
        int t = dir ? (TLEN - 1 - step) : step;
        const float* hc = g_h[cur][dir];
        float* hnx = g_h[cur ^ 1][dir];
        const uint32_t* hsh = g_hshi[cur][dir];
        const uint32_t* hsl = g_hslo[cur][dir];
        uint32_t* hshN = g_hshi[cur ^ 1][dir];
        uint32_t* hslN = g_hslo[cur ^ 1][dir];

        for (int idx = tid; idx < 2048; idx += 256) {
            int half = idx >> 10;
            int row = (idx >> 5) & 31, q = idx & 31;
            const uint32_t* src = half ? hsl : hsh;
            uint4 v = *(const uint4*)&src[(size_t)(b0 + row) * 128 + q * 4];
            char* dst = half ? sHlo : sHhi;
            *(uint4*)(dst + row * 528 + q * 16) = v;
        }
        __syncthreads();

        float acc[3][4] = {};
#pragma unroll 4
        for (int ks = 0; ks < 16; ks++) {
            uint32_t ah[4], al[4];
            ldm4(ah, aH0 + ks * 32);
            ldm4(al, aL0 + ks * 32);
#pragma unroll
            for (int ni = 0; ni < 3; ni++) {
                uint4 bb = sB4[((nb + ni) * 16 + ks) * 32 + lane];
                mma16(acc[ni], ah, bb.x, bb.y);
                mma16(acc[ni], al, bb.x, bb.y);
                mma16(acc[ni], ah, bb.z, bb.w);
            }
        }
        __syncthreads();   // sH reads done; reuse as sG

#pragma unroll
        for (int ni = 0; ni < 3; ni++) {
            int col = (nb + ni) * 8 + 2 * cc;
            *(float2*)&sG[(my + r) * 96 + col] = make_float2(acc[ni][0], acc[ni][1]);
            *(float2*)&sG[(my + r + 8) * 96 + col] = make_float2(acc[ni][2], acc[ni][3]);
        }
        __syncthreads();

        const float* xgrow = xg + ((size_t)t * BSZ + b0) * GV + C0;
        for (int idx = tid; idx < 512; idx += 256) {
            int b = idx >> 4;
            int j = (idx & 15) * 2;
            const float* xp = xgrow + (size_t)b * GV;
            int row = b0 + b;
            float2 hold = *(const float2*)&hc[(size_t)row * HV + j0 + j];
            float hv[2];
#pragma unroll
            for (int u = 0; u < 2; u++) {
                int jj = j + u;
                float xr = xp[jj], xz = xp[32 + jj], xn = xp[64 + jj];
                float hr = sG[b * 96 + jj] + sbh[jj];
                float hz = sG[b * 96 + 32 + jj] + sbh[32 + jj];
                float hn = sG[b * 96 + 64 + jj] + sbh[64 + jj];
                float rg = sigm(xr + hr);
                float zg = sigm(xz + hz);
                float ng = 2.0f * sigm(2.0f * (xn + rg * hn)) - 1.0f;
                float ho = u ? hold.y : hold.x;
                hv[u] = (1.0f - zg) * ng + zg * ho;
            }
            *(float2*)&hnx[(size_t)row * HV + j0 + j] = make_float2(hv[0], hv[1]);
            uint32_t hw, lw;
            split2pack(hv[0], hv[1], hw, lw);
            int wj = (j0 + j) >> 1;
            hshN[(size_t)row * 128 + wj] = hw;
            hslN[(size_t)row * 128 + wj] = lw;
            if (mode) {
                *(float2*)&recF[((size_t)row * TLEN + t) * H2V + dir * HV + j0 + j] =
                    make_float2(hv[0], hv[1]);
            } else {
                size_t o = ((size_t)row * TLEN + t) * 256 + dir * 128 + wj;
                recHi[o] = hw;
                recLo[o] = lw;
            }
        }
        group_barrier(grp);
        cur ^= 1;
    }
}

// ---------------- attention + output ----------------
__global__ void __launch_bounds__(256) attention_kernel(const float* __restrict__ rec2,
                                                        float* __restrict__ out) {
    __shared__ float smerged[512];
    __shared__ float sc[256];
    __shared__ float red[8];
    __shared__ float bcast;
    int b = blockIdx.x, tid = threadIdx.x;
    const float* base = rec2 + (size_t)b * (TLEN * H2V);

    smerged[tid] = base[255 * H2V + tid];
    smerged[256 + tid] = base[256 + tid];
    __syncthreads();

    int lane = tid & 31, wid = tid >> 5;
    for (int t = wid; t < TLEN; t += 8) {
        const float* row = base + (size_t)t * H2V;
        float s = 0.0f;
        for (int h = lane; h < H2V; h += 32) s += row[h] * smerged[h];
#pragma unroll
        for (int o = 16; o; o >>= 1) s += __shfl_xor_sync(0xffffffffu, s, o);
        if (lane == 0) sc[t] = s;
    }
    __syncthreads();

    float v = sc[tid];
    float m = v;
#pragma unroll
    for (int o = 16; o; o >>= 1) m = fmaxf(m, __shfl_xor_sync(0xffffffffu, m, o));
    if (lane == 0) red[wid] = m;
    __syncthreads();
    if (tid == 0) {
        float mm = red[0];
        for (int i = 1; i < 8; i++) mm = fmaxf(mm, red[i]);
        bcast = mm;
    }
    __syncthreads();
    m = bcast;
    float e = expf(v - m);
    float s = e;
#pragma unroll
    for (int o = 16; o; o >>= 1) s += __shfl_xor_sync(0xffffffffu, s, o);
    if (lane == 0) red[wid] = s;
    __syncthreads();
    if (tid == 0) {
        float ss = 0.0f;
        for (int i = 0; i < 8; i++) ss += red[i];
        bcast = ss;
    }
    __syncthreads();
    float wgt = e / bcast;
    sc[tid] = wgt;
    __syncthreads();

    float a0 = 0.0f, a1 = 0.0f;
    for (int t = 0; t < TLEN; t++) {
        float wt = sc[t];
        a0 += wt * base[(size_t)t * H2V + tid];
        a1 += wt * base[(size_t)t * H2V + 256 + tid];
    }
    float* ob = out + (size_t)b * 1024;
    ob[tid] = a0;
    ob[256 + tid] = a1;
    ob[512 + tid] = base[255 * H2V + tid];
    ob[768 + tid] = base[255 * H2V + 256 + tid];
}

// ---------------- host launcher ----------------
extern "C" void kernel_launch(void* const* d_in, const int* in_sizes, int n_in,
                              void* d_out, int out_size) {
    (void)in_sizes; (void)n_in; (void)out_size;
    const float* input = (const float*)d_in[0];
    const float* wih1f = (const float*)d_in[1];
    const float* whh1f = (const float*)d_in[2];
    const float* bih1f = (const float*)d_in[3];
    const float* bhh1f = (const float*)d_in[4];
    const float* wih1r = (const float*)d_in[5];
    const float* whh1r = (const float*)d_in[6];
    const float* bih1r = (const float*)d_in[7];
    const float* bhh1r = (const float*)d_in[8];
    const float* wih2f = (const float*)d_in[9];
    const float* whh2f = (const float*)d_in[10];
    const float* bih2f = (const float*)d_in[11];
    const float* bhh2f = (const float*)d_in[12];
    const float* wih2r = (const float*)d_in[13];
    const float* whh2r = (const float*)d_in[14];
    const float* bih2r = (const float*)d_in[15];
    const float* bhh2r = (const float*)d_in[16];

    uint4 *fW1f, *fW1r, *fW2f, *fW2r, *fH1f, *fH1r, *fH2f, *fH2r;
    float *bihP, *bhhP, *xgf, *xgr, *rec2;
    uint32_t *xinhi, *xinlo, *r1hi, *r1lo;
    cudaGetSymbolAddress((void**)&fW1f, g_fW1f);
    cudaGetSymbolAddress((void**)&fW1r, g_fW1r);
    cudaGetSymbolAddress((void**)&fW2f, g_fW2f);
    cudaGetSymbolAddress((void**)&fW2r, g_fW2r);
    cudaGetSymbolAddress((void**)&fH1f, g_fH1f);
    cudaGetSymbolAddress((void**)&fH1r, g_fH1r);
    cudaGetSymbolAddress((void**)&fH2f, g_fH2f);
    cudaGetSymbolAddress((void**)&fH2r, g_fH2r);
    cudaGetSymbolAddress((void**)&bihP, g_bihP);
    cudaGetSymbolAddress((void**)&bhhP, g_bhhP);
    cudaGetSymbolAddress((void**)&xgf, g_xgf);
    cudaGetSymbolAddress((void**)&xgr, g_xgr);
    cudaGetSymbolAddress((void**)&rec2, g_rec2);
    cudaGetSymbolAddress((void**)&xinhi, g_xinhi);
    cudaGetSymbolAddress((void**)&xinlo, g_xinlo);
    cudaGetSymbolAddress((void**)&r1hi, g_r1hi);
    cudaGetSymbolAddress((void**)&r1lo, g_r1lo);

    split_input<<<2048, 256>>>(input, xinhi, xinlo, BSZ * TLEN * (NINV / 2));
    pack_frag<<<96, 256>>>(fW1f, wih1f, NINV);
    pack_frag<<<96, 256>>>(fW1r, wih1r, NINV);
    pack_frag<<<192, 256>>>(fW2f, wih2f, H2V);
    pack_frag<<<192, 256>>>(fW2r, wih2r, H2V);
    pack_frag<<<128, 256>>>(fH1f, whh1f, HV);
    pack_frag<<<128, 256>>>(fH1r, whh1r, HV);
    pack_frag<<<128, 256>>>(fH2f, whh2f, HV);
    pack_frag<<<128, 256>>>(fH2r, whh2r, HV);
    pack_b<<<1, 768>>>(bihP + 0 * GV, bih1f);
    pack_b<<<1, 768>>>(bihP + 1 * GV, bih1r);
    pack_b<<<1, 768>>>(bihP + 2 * GV, bih2f);
    pack_b<<<1, 768>>>(bihP + 3 * GV, bih2r);
    pack_b<<<1, 768>>>(bhhP + 0 * GV, bhh1f);
    pack_b<<<1, 768>>>(bhhP + 1 * GV, bhh1r);
    pack_b<<<1, 768>>>(bhhP + 2 * GV, bhh2f);
    pack_b<<<1, 768>>>(bhhP + 3 * GV, bhh2r);

    cudaFuncSetAttribute(xg_mma<64>, cudaFuncAttributeMaxDynamicSharedMemorySize, XG_SMEM);
    cudaFuncSetAttribute(xg_mma<256>, cudaFuncAttributeMaxDynamicSharedMemorySize, XG_SMEM);
    cudaFuncSetAttribute(scan_kernel, cudaFuncAttributeMaxDynamicSharedMemorySize, SCAN_SMEM);

    // Layer 1
    xg_mma<64><<<dim3(12, 1024), 128, XG_SMEM>>>(xinhi, xinlo, fW1f, bihP + 0 * GV, xgf);
    xg_mma<64><<<dim3(12, 1024), 128, XG_SMEM>>>(xinhi, xinlo, fW1r, bihP + 1 * GV, xgr);
    zero_h<<<256, 256>>>();
    scan_kernel<<<128, 256, SCAN_SMEM>>>(fH1f, fH1r, bhhP + 0 * GV, bhhP + 1 * GV,
                                         xgf, xgr, nullptr, r1hi, r1lo, 0);
    // Layer 2
    xg_mma<256><<<dim3(12, 1024), 128, XG_SMEM>>>(r1hi, r1lo, fW2f, bihP + 2 * GV, xgf);
    xg_mma<256><<<dim3(12, 1024), 128, XG_SMEM>>>(r1hi, r1lo, fW2r, bihP + 3 * GV, xgr);
    zero_h<<<256, 256>>>();
    scan_kernel<<<128, 256, SCAN_SMEM>>>(fH2f, fH2r, bhhP + 2 * GV, bhhP + 3 * GV,
                                         xgf, xgr, rec2, nullptr, nullptr, 1);
    // Attention + output
    attention_kernel<<<256, 256>>>(rec2, (float*)d_out);
}

// round 14
// speedup vs baseline: 2.7258x; 1.1447x over previous
#include <cuda_runtime.h>
#include <math.h>
#include <stdint.h>

#define BSZ  256
#define TLEN 256
#define NINV 128
#define HV   256
#define GV   768   // 3H
#define H2V  512   // 2H

// ---------------- device scratch ----------------
__device__ uint4 g_fW1f[96 * 8 * 32];     // wih L1, Din=128
__device__ uint4 g_fW1r[96 * 8 * 32];
__device__ uint4 g_fW2f[96 * 32 * 32];    // wih L2, Din=512
__device__ uint4 g_fW2r[96 * 32 * 32];
__device__ uint4 g_fH1f[96 * 16 * 32];    // whh, Din=256
__device__ uint4 g_fH1r[96 * 16 * 32];
__device__ uint4 g_fH2f[96 * 16 * 32];
__device__ uint4 g_fH2r[96 * 16 * 32];
__device__ float g_bihP[4][GV];
__device__ float g_bhhP[4][GV];
__device__ float g_xgf[(size_t)TLEN * BSZ * GV];
__device__ float g_xgr[(size_t)TLEN * BSZ * GV];
__device__ uint32_t g_xinhi[(size_t)BSZ * TLEN * (NINV / 2)];
__device__ uint32_t g_xinlo[(size_t)BSZ * TLEN * (NINV / 2)];
__device__ uint32_t g_r1hi[(size_t)BSZ * TLEN * (H2V / 2)];
__device__ uint32_t g_r1lo[(size_t)BSZ * TLEN * (H2V / 2)];
__device__ float g_rec2[(size_t)BSZ * TLEN * H2V];
__device__ uint32_t g_hshi[2][2][BSZ * (HV / 2)];   // split h state (sole h storage)
__device__ uint32_t g_hslo[2][2][BSZ * (HV / 2)];
__device__ unsigned g_gcnt[16 * 32];
__device__ volatile unsigned g_ggen[16 * 32];

// Packed column c = jt*96 + gate*32 + jl  <->  orig row = gate*256 + jt*32 + jl
__device__ __forceinline__ int orig_row(int c) {
    int g = (c % 96) >> 5;
    int jt = c / 96;
    int jl = c & 31;
    return g * HV + jt * 32 + jl;
}

// ---------------- bf16 helpers ----------------
__device__ __forceinline__ uint16_t bf16_rn(float x) {
    uint16_t u;
    asm("cvt.rn.bf16.f32 %0, %1;" : "=h"(u) : "f"(x));
    return u;
}
__device__ __forceinline__ void split2pack(float a, float b, uint32_t& hw, uint32_t& lw) {
    uint16_t ha = bf16_rn(a);
    float hfa = __uint_as_float((uint32_t)ha << 16);
    uint16_t la = bf16_rn(a - hfa);
    uint16_t hb = bf16_rn(b);
    float hfb = __uint_as_float((uint32_t)hb << 16);
    uint16_t lb = bf16_rn(b - hfb);
    hw = (uint32_t)ha | ((uint32_t)hb << 16);
    lw = (uint32_t)la | ((uint32_t)lb << 16);
}
__device__ __forceinline__ uint32_t smem_u32(const void* p) {
    return (uint32_t)__cvta_generic_to_shared(p);
}
__device__ __forceinline__ void ldm4(uint32_t* a, uint32_t addr) {
    asm volatile("ldmatrix.sync.aligned.m8n8.x4.shared.b16 {%0,%1,%2,%3}, [%4];"
                 : "=r"(a[0]), "=r"(a[1]), "=r"(a[2]), "=r"(a[3]) : "r"(addr));
}
__device__ __forceinline__ void mma16(float* c, const uint32_t* a, uint32_t b0, uint32_t b1) {
    asm volatile("mma.sync.aligned.m16n8k16.row.col.f32.bf16.bf16.f32 "
                 "{%0,%1,%2,%3},{%4,%5,%6,%7},{%8,%9},{%0,%1,%2,%3};"
                 : "+f"(c[0]), "+f"(c[1]), "+f"(c[2]), "+f"(c[3])
                 : "r"(a[0]), "r"(a[1]), "r"(a[2]), "r"(a[3]), "r"(b0), "r"(b1));
}
__device__ __forceinline__ float sigm(float x) {
    float e = __expf(-x);
    return __fdividef(1.0f, 1.0f + e);
}
__device__ __forceinline__ void cpa16(uint32_t dst, const void* src) {
    asm volatile("cp.async.cg.shared.global [%0], [%1], 16;" :: "r"(dst), "l"(src));
}
#define CP_COMMIT() asm volatile("cp.async.commit_group;" ::: "memory")
#define CP_WAIT0()  asm volatile("cp.async.wait_group 0;" ::: "memory")
#define CP_WAIT1()  asm volatile("cp.async.wait_group 1;" ::: "memory")

// ---------------- packing ----------------
__global__ void pack_frag(uint4* __restrict__ dst, const float* __restrict__ src, int Din) {
    int KS = Din >> 4;
    int tot = 96 * KS * 32;
    for (int idx = blockIdx.x * blockDim.x + threadIdx.x; idx < tot;
         idx += gridDim.x * blockDim.x) {
        int lane = idx & 31;
        int ks = (idx >> 5) % KS;
        int nt = idx / (32 * KS);
        int cg = nt * 8 + (lane >> 2);
        int r = orig_row(cg);
        int k0 = ks * 16 + (lane & 3) * 2;
        const float* s = src + (size_t)r * Din;
        uint32_t bh0, bl0, bh1, bl1;
        split2pack(s[k0], s[k0 + 1], bh0, bl0);
        split2pack(s[k0 + 8], s[k0 + 9], bh1, bl1);
        dst[idx] = make_uint4(bh0, bh1, bl0, bl1);
    }
}

__global__ void pack_b(float* __restrict__ dst, const float* __restrict__ src) {
    int c = threadIdx.x;
    if (c < GV) dst[c] = src[orig_row(c)];
}

__global__ void zero_h() {
    int idx = blockIdx.x * blockDim.x + threadIdx.x;
    int stride = gridDim.x * blockDim.x;
    for (int i = idx; i < 2 * BSZ * (HV / 2); i += stride) {
        ((uint32_t*)g_hshi)[i] = 0u;
        ((uint32_t*)g_hslo)[i] = 0u;
    }
}

__global__ void split_input(const float* __restrict__ src, uint32_t* __restrict__ hi,
                            uint32_t* __restrict__ lo, int words) {
    for (int idx = blockIdx.x * blockDim.x + threadIdx.x; idx < words;
         idx += gridDim.x * blockDim.x) {
        float2 v = *(const float2*)&src[(size_t)idx * 2];
        uint32_t hw, lw;
        split2pack(v.x, v.y, hw, lw);
        hi[idx] = hw;
        lo[idx] = lw;
    }
}

// ---------------- input-gate GEMM (bf16x3, cp.async double-buffered) ----------------
#define XG_STAGE 34816
#define XG_SMEM (2 * XG_STAGE)
extern __shared__ char smem_raw[];

template <int KW>
__device__ __forceinline__ void xg_issue(uint32_t st, int tid, int m0, int n0blk, int ch,
                                         const uint32_t* __restrict__ Ahi,
                                         const uint32_t* __restrict__ Alo,
                                         const uint4* __restrict__ fB) {
    const int KSTEPS = KW >> 3;
    int kc = ch * 32;
    for (int idx = tid; idx < 2048; idx += 128) {
        if (idx < 512) {
            int row = idx >> 3, q = idx & 7;
            cpa16(st + row * 144 + q * 16, &Ahi[(size_t)(m0 + row) * KW + kc + q * 4]);
        } else if (idx < 1024) {
            int e = idx - 512, row = e >> 3, q = e & 7;
            cpa16(st + 9216 + row * 144 + q * 16, &Alo[(size_t)(m0 + row) * KW + kc + q * 4]);
        } else {
            int e = idx - 1024;
            int nt = e >> 7, ks = (e >> 5) & 3, ln = e & 31;
            cpa16(st + 18432 + e * 16,
                  &fB[((size_t)(n0blk + nt) * KSTEPS + ch * 4 + ks) * 32 + ln]);
        }
    }
    CP_COMMIT();
}

template <int KW>
__global__ void __launch_bounds__(128) xg_mma(const uint32_t* __restrict__ Ahi,
                                              const uint32_t* __restrict__ Alo,
                                              const uint4* __restrict__ fB,
                                              const float* __restrict__ bias,
                                              float* __restrict__ out) {
    const int NC = KW / 32;
    uint32_t sb = smem_u32(smem_raw);
    int tid = threadIdx.x;
    int w = tid >> 5, lane = tid & 31;
    int m0 = blockIdx.y * 64;
    int n0blk = blockIdx.x * 8;
    int wm = (w & 1) * 32;
    int wn = (w >> 1) * 4;
    int r = lane >> 2, cc = lane & 3;
    int rl = lane & 15, kh = (lane >> 4) * 16;

    xg_issue<KW>(sb, tid, m0, n0blk, 0, Ahi, Alo, fB);

    float acc[2][4][4] = {};
    for (int ch = 0; ch < NC; ch++) {
        int s = ch & 1;
        if (ch + 1 < NC) {
            xg_issue<KW>(sb + (s ^ 1) * XG_STAGE, tid, m0, n0blk, ch + 1, Ahi, Alo, fB);
            CP_WAIT1();
        } else {
            CP_WAIT0();
        }
        __syncthreads();
        uint32_t stg = sb + s * XG_STAGE;
        uint32_t aH0 = stg + (wm + rl) * 144 + kh;
        uint32_t aH1 = aH0 + 16 * 144;
        uint32_t aL0 = aH0 + 9216;
        uint32_t aL1 = aL0 + 16 * 144;
        const uint4* sB = (const uint4*)(smem_raw + s * XG_STAGE + 18432);
#pragma unroll
        for (int ks = 0; ks < 4; ks++) {
            uint32_t ah0[4], ah1[4], al0[4], al1[4];
            ldm4(ah0, aH0 + ks * 32);
            ldm4(ah1, aH1 + ks * 32);
            ldm4(al0, aL0 + ks * 32);
            ldm4(al1, aL1 + ks * 32);
#pragma unroll
            for (int ni = 0; ni < 4; ni++) {
                uint4 bb = sB[((wn + ni) * 4 + ks) * 32 + lane];
                mma16(acc[0][ni], ah0, bb.x, bb.y);
                mma16(acc[1][ni], ah1, bb.x, bb.y);
                mma16(acc[0][ni], al0, bb.x, bb.y);
                mma16(acc[1][ni], al1, bb.x, bb.y);
                mma16(acc[0][ni], ah0, bb.z, bb.w);
                mma16(acc[1][ni], ah1, bb.z, bb.w);
            }
        }
        __syncthreads();
    }
#pragma unroll
    for (int mi = 0; mi < 2; mi++) {
#pragma unroll
        for (int half = 0; half < 2; half++) {
            int row = m0 + wm + mi * 16 + r + half * 8;
            int b = row >> 8, t = row & 255;
            float* orow = out + ((size_t)t * BSZ + b) * GV;
#pragma unroll
            for (int ni = 0; ni < 4; ni++) {
                int col = (n0blk + wn + ni) * 8 + 2 * cc;
                float2 bs = *(const float2*)&bias[col];
                float2 o;
                o.x = acc[mi][ni][half * 2 + 0] + bs.x;
                o.y = acc[mi][ni][half * 2 + 1] + bs.y;
                *(float2*)&orow[col] = o;
            }
        }
    }
}

// ---------------- recurrent scan (bf16x3, fused register epilogue) ----------------
#define SB_BYTES (96 * 1024)
#define SH_BYTES (32 * 528)
#define XB_OFF (SB_BYTES + 2 * SH_BYTES)          // 132096
#define XB_BYTES 12288                            // 32 rows x 96 floats
#define SCAN_SMEM (XB_OFF + 2 * XB_BYTES)         // 156672
__global__ void __launch_bounds__(256, 1) scan_kernel(const uint4* __restrict__ fWf,
                                                      const uint4* __restrict__ fWr,
                                                      const float* __restrict__ bhf,
                                                      const float* __restrict__ bhr,
                                                      const float* __restrict__ xgF,
                                                      const float* __restrict__ xgR,
                                                      float* __restrict__ recF,
                                                      uint32_t* __restrict__ recHi,
                                                      uint32_t* __restrict__ recLo,
                                                      int mode) {
    uint4* sB4 = (uint4*)smem_raw;
    char* sHhi = smem_raw + SB_BYTES;
    char* sHlo = sHhi + SH_BYTES;
    __shared__ float sbh[96];

    int tid = threadIdx.x;
    int w = tid >> 5, lane = tid & 31;
    int dir = blockIdx.x >> 6;
    int tile = blockIdx.x & 63;
    int bt = tile >> 3, jt = tile & 7;
    int b0 = bt * 32, j0 = jt * 32, C0 = jt * 96;
    int grp = (int)(blockIdx.x >> 3);
    unsigned* gcnt = &g_gcnt[grp * 32];
    volatile unsigned* ggen = &g_ggen[grp * 32];

    const uint4* fW = dir ? fWr : fWf;
    const float* bh = dir ? bhr : bhf;
    const float* xg = dir ? xgR : xgF;

    for (int idx = tid; idx < 12 * 16 * 32; idx += 256)
        sB4[idx] = fW[(size_t)jt * (12 * 16 * 32) + idx];
    if (tid < 96) sbh[tid] = bh[C0 + tid];

    // warp/thread geometry
    int wx = w & 3, my = (w >> 2) * 16;
    int r = lane >> 2, cc = lane & 3;
    int rl = lane & 15, kh = (lane >> 4) * 16;
    uint32_t sbase = smem_u32(smem_raw);
    uint32_t aH0 = sbase + SB_BYTES + (my + rl) * 528 + kh;
    uint32_t aL0 = aH0 + SH_BYTES;
    int jl0 = wx * 8 + 2 * cc;                  // even j within 32-block
    int wj = (j0 + jl0) >> 1;                   // h-split word index

    // prefetch xg tile for step 0
    {
        int t0 = dir ? (TLEN - 1) : 0;
        const float* src = xg + ((size_t)t0 * BSZ + b0) * GV + C0;
        for (int i = tid; i < 768; i += 256) {
            int row = i / 24, q = i % 24;
            cpa16(sbase + XB_OFF + row * 384 + q * 16, &src[(size_t)row * GV + q * 4]);
        }
        CP_COMMIT();
    }

    int cur = 0;
    for (int step = 0; step < TLEN; step++) {
        int t = dir ? (TLEN - 1 - step) : step;
        const uint32_t* hsh = g_hshi[cur][dir];
        const uint32_t* hsl = g_hslo[cur][dir];
        uint32_t* hshN = g_hshi[cur ^ 1][dir];
        uint32_t* hslN = g_hslo[cur ^ 1][dir];

        // prefetch xg for next step into alternate buffer
        {
            int sn = step + 1 < TLEN ? step + 1 : TLEN - 1;
            int tn = dir ? (TLEN - 1 - sn) : sn;
            const float* src = xg + ((size_t)tn * BSZ + b0) * GV + C0;
            uint32_t dstb = sbase + XB_OFF + ((step + 1) & 1) * XB_BYTES;
            for (int i = tid; i < 768; i += 256) {
                int row = i / 24, q = i % 24;
                cpa16(dstb + row * 384 + q * 16, &src[(size_t)row * GV + q * 4]);
            }
            CP_COMMIT();
        }

        // h tile: global split -> smem
        for (int idx = tid; idx < 2048; idx += 256) {
            int half = idx >> 10;
            int row = (idx >> 5) & 31, q = idx & 31;
            const uint32_t* src = half ? hsl : hsh;
            uint4 v = *(const uint4*)&src[(size_t)(b0 + row) * 128 + q * 4];
            char* dst = half ? sHlo : sHhi;
            *(uint4*)(dst + row * 528 + q * 16) = v;
        }
        CP_WAIT1();          // current-step xg buffer landed
        __syncthreads();     // covers h smem + xg buffer

        float acc[3][4] = {};
#pragma unroll 4
        for (int ks = 0; ks < 16; ks++) {
            uint32_t ah[4], al[4];
            ldm4(ah, aH0 + ks * 32);
            ldm4(al, aL0 + ks * 32);
#pragma unroll
            for (int ni = 0; ni < 3; ni++) {
                uint4 bb = sB4[(((wx + ni * 4)) * 16 + ks) * 32 + lane];
                mma16(acc[ni], ah, bb.x, bb.y);
                mma16(acc[ni], al, bb.x, bb.y);
                mma16(acc[ni], ah, bb.z, bb.w);
            }
        }

        // fused GRU epilogue in registers
        const float* xb = (const float*)(smem_raw + XB_OFF + (step & 1) * XB_BYTES);
        float2 br = *(const float2*)&sbh[jl0];
        float2 bz = *(const float2*)&sbh[32 + jl0];
        float2 bn = *(const float2*)&sbh[64 + jl0];
        float2 rec_val[2];
        uint32_t rec_hw[2], rec_lw[2];
        int rows[2];
#pragma unroll
        for (int mi = 0; mi < 2; mi++) {
            int rl2 = my + r + mi * 8;
            int row = b0 + rl2;
            rows[mi] = row;
            const float* xrow = xb + rl2 * 96;
            float2 x_r = *(const float2*)&xrow[jl0];
            float2 x_z = *(const float2*)&xrow[32 + jl0];
            float2 x_n = *(const float2*)&xrow[64 + jl0];
            uint32_t hwo = *(const uint32_t*)(sHhi + rl2 * 528 + (j0 + jl0) * 2);
            uint32_t lwo = *(const uint32_t*)(sHlo + rl2 * 528 + (j0 + jl0) * 2);
            float ho0 = __uint_as_float(hwo << 16) + __uint_as_float(lwo << 16);
            float ho1 = __uint_as_float(hwo & 0xFFFF0000u) + __uint_as_float(lwo & 0xFFFF0000u);
            float hr0 = acc[0][mi * 2 + 0] + br.x;
            float hz0 = acc[1][mi * 2 + 0] + bz.x;
            float hn0 = acc[2][mi * 2 + 0] + bn.x;
            float rg0 = sigm(x_r.x + hr0);
            float zg0 = sigm(x_z.x + hz0);
            float ng0 = 2.0f * sigm(2.0f * (x_n.x + rg0 * hn0)) - 1.0f;
            float hv0 = (1.0f - zg0) * ng0 + zg0 * ho0;
            float hr1 = acc[0][mi * 2 + 1] + br.y;
            float hz1 = acc[1][mi * 2 + 1] + bz.y;
            float hn1 = acc[2][mi * 2 + 1] + bn.y;
            float rg1 = sigm(x_r.y + hr1);
            float zg1 = sigm(x_z.y + hz1);
            float ng1 = 2.0f * sigm(2.0f * (x_n.y + rg1 * hn1)) - 1.0f;
            float hv1 = (1.0f - zg1) * ng1 + zg1 * ho1;
            uint32_t hw, lw;
            split2pack(hv0, hv1, hw, lw);
            hshN[(size_t)row * 128 + wj] = hw;
            hslN[(size_t)row * 128 + wj] = lw;
            rec_val[mi] = make_float2(hv0, hv1);
            rec_hw[mi] = hw;
            rec_lw[mi] = lw;
        }
        __syncthreads();     // all h-split stores issued (also guards sH reads)

        // barrier arrive (tid 0), then overlap recOut stores with peers
        unsigned mygen = 0;
        int flipped = 0;
        if (tid == 0) {
            mygen = *ggen;
            __threadfence();
            unsigned tt = atomicAdd(gcnt, 1u);
            if (tt == 7u) {
                *gcnt = 0u;
                __threadfence();
                *ggen = mygen + 1u;
                flipped = 1;
            }
        }
#pragma unroll
        for (int mi = 0; mi < 2; mi++) {
            if (mode) {
                *(float2*)&recF[((size_t)rows[mi] * TLEN + t) * H2V + dir * HV + j0 + jl0] =
                    rec_val[mi];
            } else {
                size_t o = ((size_t)rows[mi] * TLEN + t) * 256 + dir * 128 + wj;
                recHi[o] = rec_hw[mi];
                recLo[o] = rec_lw[mi];
            }
        }
        if (tid == 0 && !flipped) {
            while (*ggen == mygen) { __nanosleep(20); }
        }
        if (tid == 0) __threadfence();
        __syncthreads();
        cur ^= 1;
    }
}

// ---------------- attention + output ----------------
__global__ void __launch_bounds__(256) attention_kernel(const float* __restrict__ rec2,
                                                        float* __restrict__ out) {
    __shared__ float smerged[512];
    __shared__ float sc[256];
    __shared__ float red[8];
    __shared__ float bcast;
    int b = blockIdx.x, tid = threadIdx.x;
    const float* base = rec2 + (size_t)b * (TLEN * H2V);

    smerged[tid] = base[255 * H2V + tid];
    smerged[256 + tid] = base[256 + tid];
    __syncthreads();

    int lane = tid & 31, wid = tid >> 5;
    for (int t = wid; t < TLEN; t += 8) {
        const float* row = base + (size_t)t * H2V;
        float s = 0.0f;
        for (int h = lane; h < H2V; h += 32) s += row[h] * smerged[h];
#pragma unroll
        for (int o = 16; o; o >>= 1) s += __shfl_xor_sync(0xffffffffu, s, o);
        if (lane == 0) sc[t] = s;
    }
    __syncthreads();

    float v = sc[tid];
    float m = v;
#pragma unroll
    for (int o = 16; o; o >>= 1) m = fmaxf(m, __shfl_xor_sync(0xffffffffu, m, o));
    if (lane == 0) red[wid] = m;
    __syncthreads();
    if (tid == 0) {
        float mm = red[0];
        for (int i = 1; i < 8; i++) mm = fmaxf(mm, red[i]);
        bcast = mm;
    }
    __syncthreads();
    m = bcast;
    float e = expf(v - m);
    float s = e;
#pragma unroll
    for (int o = 16; o; o >>= 1) s += __shfl_xor_sync(0xffffffffu, s, o);
    if (lane == 0) red[wid] = s;
    __syncthreads();
    if (tid == 0) {
        float ss = 0.0f;
        for (int i = 0; i < 8; i++) ss += red[i];
        bcast = ss;
    }
    __syncthreads();
    float wgt = e / bcast;
    sc[tid] = wgt;
    __syncthreads();

    float a0 = 0.0f, a1 = 0.0f;
    for (int t = 0; t < TLEN; t++) {
        float wt = sc[t];
        a0 += wt * base[(size_t)t * H2V + tid];
        a1 += wt * base[(size_t)t * H2V + 256 + tid];
    }
    float* ob = out + (size_t)b * 1024;
    ob[tid] = a0;
    ob[256 + tid] = a1;
    ob[512 + tid] = base[255 * H2V + tid];
    ob[768 + tid] = base[255 * H2V + 256 + tid];
}

// ---------------- host launcher ----------------
extern "C" void kernel_launch(void* const* d_in, const int* in_sizes, int n_in,
                              void* d_out, int out_size) {
    (void)in_sizes; (void)n_in; (void)out_size;
    const float* input = (const float*)d_in[0];
    const float* wih1f = (const float*)d_in[1];
    const float* whh1f = (const float*)d_in[2];
    const float* bih1f = (const float*)d_in[3];
    const float* bhh1f = (const float*)d_in[4];
    const float* wih1r = (const float*)d_in[5];
    const float* whh1r = (const float*)d_in[6];
    const float* bih1r = (const float*)d_in[7];
    const float* bhh1r = (const float*)d_in[8];
    const float* wih2f = (const float*)d_in[9];
    const float* whh2f = (const float*)d_in[10];
    const float* bih2f = (const float*)d_in[11];
    const float* bhh2f = (const float*)d_in[12];
    const float* wih2r = (const float*)d_in[13];
    const float* whh2r = (const float*)d_in[14];
    const float* bih2r = (const float*)d_in[15];
    const float* bhh2r = (const float*)d_in[16];

    uint4 *fW1f, *fW1r, *fW2f, *fW2r, *fH1f, *fH1r, *fH2f, *fH2r;
    float *bihP, *bhhP, *xgf, *xgr, *rec2;
    uint32_t *xinhi, *xinlo, *r1hi, *r1lo;
    cudaGetSymbolAddress((void**)&fW1f, g_fW1f);
    cudaGetSymbolAddress((void**)&fW1r, g_fW1r);
    cudaGetSymbolAddress((void**)&fW2f, g_fW2f);
    cudaGetSymbolAddress((void**)&fW2r, g_fW2r);
    cudaGetSymbolAddress((void**)&fH1f, g_fH1f);
    cudaGetSymbolAddress((void**)&fH1r, g_fH1r);
    cudaGetSymbolAddress((void**)&fH2f, g_fH2f);
    cudaGetSymbolAddress((void**)&fH2r, g_fH2r);
    cudaGetSymbolAddress((void**)&bihP, g_bihP);
    cudaGetSymbolAddress((void**)&bhhP, g_bhhP);
    cudaGetSymbolAddress((void**)&xgf, g_xgf);
    cudaGetSymbolAddress((void**)&xgr, g_xgr);
    cudaGetSymbolAddress((void**)&rec2, g_rec2);
    cudaGetSymbolAddress((void**)&xinhi, g_xinhi);
    cudaGetSymbolAddress((void**)&xinlo, g_xinlo);
    cudaGetSymbolAddress((void**)&r1hi, g_r1hi);
    cudaGetSymbolAddress((void**)&r1lo, g_r1lo);

    split_input<<<2048, 256>>>(input, xinhi, xinlo, BSZ * TLEN * (NINV / 2));
    pack_frag<<<96, 256>>>(fW1f, wih1f, NINV);
    pack_frag<<<96, 256>>>(fW1r, wih1r, NINV);
    pack_frag<<<192, 256>>>(fW2f, wih2f, H2V);
    pack_frag<<<192, 256>>>(fW2r, wih2r, H2V);
    pack_frag<<<128, 256>>>(fH1f, whh1f, HV);
    pack_frag<<<128, 256>>>(fH1r, whh1r, HV);
    pack_frag<<<128, 256>>>(fH2f, whh2f, HV);
    pack_frag<<<128, 256>>>(fH2r, whh2r, HV);
    pack_b<<<1, 768>>>(bihP + 0 * GV, bih1f);
    pack_b<<<1, 768>>>(bihP + 1 * GV, bih1r);
    pack_b<<<1, 768>>>(bihP + 2 * GV, bih2f);
    pack_b<<<1, 768>>>(bihP + 3 * GV, bih2r);
    pack_b<<<1, 768>>>(bhhP + 0 * GV, bhh1f);
    pack_b<<<1, 768>>>(bhhP + 1 * GV, bhh1r);
    pack_b<<<1, 768>>>(bhhP + 2 * GV, bhh2f);
    pack_b<<<1, 768>>>(bhhP + 3 * GV, bhh2r);

    cudaFuncSetAttribute(xg_mma<64>, cudaFuncAttributeMaxDynamicSharedMemorySize, XG_SMEM);
    cudaFuncSetAttribute(xg_mma<256>, cudaFuncAttributeMaxDynamicSharedMemorySize, XG_SMEM);
    cudaFuncSetAttribute(scan_kernel, cudaFuncAttributeMaxDynamicSharedMemorySize, SCAN_SMEM);

    // Layer 1
    xg_mma<64><<<dim3(12, 1024), 128, XG_SMEM>>>(xinhi, xinlo, fW1f, bihP + 0 * GV, xgf);
    xg_mma<64><<<dim3(12, 1024), 128, XG_SMEM>>>(xinhi, xinlo, fW1r, bihP + 1 * GV, xgr);
    zero_h<<<256, 256>>>();
    scan_kernel<<<128, 256, SCAN_SMEM>>>(fH1f, fH1r, bhhP + 0 * GV, bhhP + 1 * GV,
                                         xgf, xgr, nullptr, r1hi, r1lo, 0);
    // Layer 2
    xg_mma<256><<<dim3(12, 1024), 128, XG_SMEM>>>(r1hi, r1lo, fW2f, bihP + 2 * GV, xgf);
    xg_mma<256><<<dim3(12, 1024), 128, XG_SMEM>>>(r1hi, r1lo, fW2r, bihP + 3 * GV, xgr);
    zero_h<<<256, 256>>>();
    scan_kernel<<<128, 256, SCAN_SMEM>>>(fH2f, fH2r, bhhP + 2 * GV, bhhP + 3 * GV,
                                         xgf, xgr, rec2, nullptr, nullptr, 1);
    // Attention + output
    attention_kernel<<<256, 256>>>(rec2, (float*)d_out);
}